// round 6
// baseline (speedup 1.0000x reference)
#include <cuda_runtime.h>
#include <cuda_bf16.h>
#include <cstdint>

#define BATCH 4
#define SEQ   4096
#define DIM   256
#define RSB   528

static __device__ __align__(16) __nv_bfloat16 g_Qh[(size_t)BATCH * SEQ * DIM];
static __device__ __align__(16) __nv_bfloat16 g_Ql[(size_t)BATCH * SEQ * DIM];
static __device__ __align__(16) __nv_bfloat16 g_Kh[(size_t)BATCH * SEQ * DIM];
static __device__ __align__(16) __nv_bfloat16 g_Kl[(size_t)BATCH * SEQ * DIM];
static __device__ __align__(16) __nv_bfloat16 g_Vh[(size_t)BATCH * SEQ * DIM];
static __device__ __align__(16) __nv_bfloat16 g_Vl[(size_t)BATCH * SEQ * DIM];
static __device__ __align__(16) __nv_bfloat16 g_Wh[3 * DIM * DIM];
static __device__ __align__(16) __nv_bfloat16 g_Wl[3 * DIM * DIM];

__device__ __forceinline__ uint32_t smem_to_u32(const void* p) {
    uint32_t a;
    asm("{ .reg .u64 t; cvta.to.shared.u64 t, %1; cvt.u32.u64 %0, t; }"
        : "=r"(a) : "l"(p));
    return a;
}
__device__ __forceinline__ void mma_bf16(float* d, const uint32_t* a, const uint32_t* b) {
    asm volatile(
        "mma.sync.aligned.m16n8k16.row.col.f32.bf16.bf16.f32 "
        "{%0,%1,%2,%3}, {%4,%5,%6,%7}, {%8,%9}, {%0,%1,%2,%3};"
        : "+f"(d[0]), "+f"(d[1]), "+f"(d[2]), "+f"(d[3])
        : "r"(a[0]), "r"(a[1]), "r"(a[2]), "r"(a[3]), "r"(b[0]), "r"(b[1]));
}
__device__ __forceinline__ void ldsm_x4(uint32_t* r, uint32_t addr) {
    asm volatile("ldmatrix.sync.aligned.m8n8.x4.shared.b16 {%0,%1,%2,%3}, [%4];"
        : "=r"(r[0]), "=r"(r[1]), "=r"(r[2]), "=r"(r[3]) : "r"(addr));
}
__device__ __forceinline__ void ldsm_x4_t(uint32_t* r, uint32_t addr) {
    asm volatile("ldmatrix.sync.aligned.m8n8.x4.trans.shared.b16 {%0,%1,%2,%3}, [%4];"
        : "=r"(r[0]), "=r"(r[1]), "=r"(r[2]), "=r"(r[3]) : "r"(addr));
}
__device__ __forceinline__ void cp16(uint32_t dst, const void* src) {
    asm volatile("cp.async.cg.shared.global [%0], [%1], 16;" :: "r"(dst), "l"(src));
}
#define CP_COMMIT() asm volatile("cp.async.commit_group;" ::: "memory")
#define CP_WAIT(n)  asm volatile("cp.async.wait_group %0;" :: "n"(n) : "memory")

__device__ __forceinline__ float ex2f(float x) {
    float y;
    asm("ex2.approx.ftz.f32 %0, %1;" : "=f"(y) : "f"(x));
    return y;
}
__device__ __forceinline__ uint32_t pack_bf(__nv_bfloat16 a, __nv_bfloat16 b) {
    return (uint32_t)__bfloat16_as_ushort(a) | ((uint32_t)__bfloat16_as_ushort(b) << 16);
}
__device__ __forceinline__ void split2(float x, __nv_bfloat16& h, __nv_bfloat16& l) {
    h = __float2bfloat16(x);
    l = __float2bfloat16(x - __bfloat162float(h));
}

// ---------------------------------------------------------------------------
__global__ __launch_bounds__(256) void split_w_kernel(
    const float* __restrict__ Wq, const float* __restrict__ Wk,
    const float* __restrict__ Wv)
{
    const int wsel = blockIdx.y;
    const float* W = (wsel == 0) ? Wq : (wsel == 1) ? Wk : Wv;
    int idx = (blockIdx.x * 256 + threadIdx.x) * 4;
    float4 v = *(const float4*)&W[idx];
    __nv_bfloat16 h[4], l[4];
    split2(v.x, h[0], l[0]); split2(v.y, h[1], l[1]);
    split2(v.z, h[2], l[2]); split2(v.w, h[3], l[3]);
    size_t base = (size_t)wsel * DIM * DIM + idx;
    *(uint2*)&g_Wh[base] = make_uint2(pack_bf(h[0], h[1]), pack_bf(h[2], h[3]));
    *(uint2*)&g_Wl[base] = make_uint2(pack_bf(l[0], l[1]), pack_bf(l[2], l[3]));
}

// ---------------------------------------------------------------------------
// Projections (unchanged from R4, proven ~70us)
// ---------------------------------------------------------------------------
#define PXH_OFF 0
#define PXL_OFF (128 * RSB)
#define PW_OFF  (PXL_OFF + 128 * RSB)
#define PWBUF   (32 * RSB)
#define PROJ_SMEM (PW_OFF + 4 * PWBUF)

__global__ __launch_bounds__(256, 1) void proj_mma(
    const float* __restrict__ x,
    const float* __restrict__ bq, const float* __restrict__ bk,
    const float* __restrict__ bv)
{
    extern __shared__ char smem[];
    const uint32_t sb = smem_to_u32(smem);
    const int tid = threadIdx.x;
    const int lane = tid & 31;
    const int w = tid >> 5;
    const int m0 = blockIdx.x * 128;

    const uint32_t sXH = sb + PXH_OFF, sXL = sb + PXL_OFF;
    uint32_t sWH[2] = {sb + PW_OFF, sb + PW_OFF + 2 * PWBUF};
    uint32_t sWL[2] = {sb + PW_OFF + PWBUF, sb + PW_OFF + 3 * PWBUF};

#pragma unroll
    for (int i = 0; i < 4; i++) {
        int idx = tid + i * 256;
        int row = idx >> 5, c16 = idx & 31;
        uint32_t d = (uint32_t)row * RSB + c16 * 16;
        size_t g = (size_t)row * DIM + c16 * 8;
        cp16(sWH[0] + d, g_Wh + g);
        cp16(sWL[0] + d, g_Wl + g);
    }
    CP_COMMIT();

#pragma unroll
    for (int i = 0; i < 32; i++) {
        int idx = tid + i * 256;
        int row = idx >> 6, c4 = idx & 63;
        float4 v = *(const float4*)&x[(size_t)(m0 + row) * DIM + c4 * 4];
        __nv_bfloat16 h[4], l[4];
        split2(v.x, h[0], l[0]); split2(v.y, h[1], l[1]);
        split2(v.z, h[2], l[2]); split2(v.w, h[3], l[3]);
        uint32_t d = (uint32_t)row * RSB + c4 * 8;
        *(uint2*)(smem + PXH_OFF + d) = make_uint2(pack_bf(h[0], h[1]), pack_bf(h[2], h[3]));
        *(uint2*)(smem + PXL_OFF + d) = make_uint2(pack_bf(l[0], l[1]), pack_bf(l[2], l[3]));
    }

    const uint32_t aoff = (uint32_t)(16 * w + (lane & 15)) * RSB + ((lane & 16) ? 16u : 0u);
    const uint32_t boff = (uint32_t)((lane & 7) + ((lane & 8) ? 8 : 0)) * RSB + ((lane & 16) ? 16u : 0u);

    float oacc[32][4];
#pragma unroll
    for (int i = 0; i < 32; i++)
#pragma unroll
        for (int j = 0; j < 4; j++) oacc[i][j] = 0.f;

#pragma unroll 1
    for (int c = 0; c < 24; c++) {
        const int buf = c & 1;
        if (c < 23) {
            const int wsel = (c + 1) >> 3;
            const int k0 = ((c + 1) & 7) * 32;
            const size_t gbase = (size_t)wsel * DIM * DIM + (size_t)k0 * DIM;
#pragma unroll
            for (int i = 0; i < 4; i++) {
                int idx = tid + i * 256;
                int row = idx >> 5, c16 = idx & 31;
                uint32_t d = (uint32_t)row * RSB + c16 * 16;
                size_t g = gbase + (size_t)row * DIM + c16 * 8;
                cp16(sWH[buf ^ 1] + d, g_Wh + g);
                cp16(sWL[buf ^ 1] + d, g_Wl + g);
            }
            CP_COMMIT();
            CP_WAIT(1);
        } else {
            CP_WAIT(0);
        }
        __syncthreads();

        const int kbase = (c & 7) * 32;
#pragma unroll
        for (int ks = 0; ks < 2; ks++) {
            uint32_t ah[4], al[4];
            ldsm_x4(ah, sXH + aoff + (uint32_t)(kbase + ks * 16) * 2);
            ldsm_x4(al, sXL + aoff + (uint32_t)(kbase + ks * 16) * 2);
#pragma unroll
            for (int nt = 0; nt < 16; nt++) {
                uint32_t bh[4], bl[4];
                uint32_t a = (uint32_t)ks * 16 * RSB + boff + (uint32_t)nt * 32;
                ldsm_x4_t(bh, sWH[buf] + a);
                ldsm_x4_t(bl, sWL[buf] + a);
#pragma unroll
                for (int h = 0; h < 2; h++) {
                    const int nto = nt * 2 + h;
                    mma_bf16(oacc[nto], ah, &bh[2 * h]);
                    mma_bf16(oacc[nto], ah, &bl[2 * h]);
                    mma_bf16(oacc[nto], al, &bh[2 * h]);
                }
            }
        }

        if ((c & 7) == 7) {
            const int wsel = c >> 3;
            const float* bias = (wsel == 0) ? bq : (wsel == 1) ? bk : bv;
            __nv_bfloat16* oh = (wsel == 0) ? g_Qh : (wsel == 1) ? g_Kh : g_Vh;
            __nv_bfloat16* ol = (wsel == 0) ? g_Ql : (wsel == 1) ? g_Kl : g_Vl;
            const int r0 = m0 + 16 * w + (lane >> 2);
            const size_t base0 = (size_t)r0 * DIM + (lane & 3) * 2;
            const size_t base1 = base0 + (size_t)8 * DIM;
#pragma unroll
            for (int nto = 0; nto < 32; nto++) {
                const int col = nto * 8 + (lane & 3) * 2;
                float b0 = bias[col], b1 = bias[col + 1];
                __nv_bfloat16 h0, l0, h1, l1;
                split2(oacc[nto][0] + b0, h0, l0);
                split2(oacc[nto][1] + b1, h1, l1);
                *(uint32_t*)&oh[base0 + nto * 8] = pack_bf(h0, h1);
                *(uint32_t*)&ol[base0 + nto * 8] = pack_bf(l0, l1);
                split2(oacc[nto][2] + b0, h0, l0);
                split2(oacc[nto][3] + b1, h1, l1);
                *(uint32_t*)&oh[base1 + nto * 8] = pack_bf(h0, h1);
                *(uint32_t*)&ol[base1 + nto * 8] = pack_bf(l0, l1);
                oacc[nto][0] = oacc[nto][1] = oacc[nto][2] = oacc[nto][3] = 0.f;
            }
        }
        __syncthreads();
    }
}

// ---------------------------------------------------------------------------
// Anti-phase attention. Warps 0-3 (X) and 4-7 (Y) run S/PV a half-phase
// apart so the tensor pipe stays fed through softmax windows.
// 16-key tiles; K and V each double-buffered.
// ---------------------------------------------------------------------------
#define QH_OFF 0
#define QL_OFF (128 * RSB)
#define KV_OFF (QL_OFF + 128 * RSB)
#define KVBUF  (16 * RSB)
#define ATTN_SMEM (KV_OFF + 8 * KVBUF)   // 202752
#define NT 256

__global__ __launch_bounds__(256, 1) void attn_mma(float* __restrict__ out)
{
    extern __shared__ char smem[];
    const uint32_t sb = smem_to_u32(smem);
    const int tid = threadIdx.x;
    const int lane = tid & 31;
    const int w = tid >> 5;
    const int grp = w >> 2;
    const int b = blockIdx.y;
    const int q0 = blockIdx.x * 128;

    const uint32_t sQH = sb + QH_OFF, sQL = sb + QL_OFF;
    uint32_t sKH[2] = {sb + KV_OFF,             sb + KV_OFF + 2 * KVBUF};
    uint32_t sKL[2] = {sb + KV_OFF + KVBUF,     sb + KV_OFF + 3 * KVBUF};
    uint32_t sVH[2] = {sb + KV_OFF + 4 * KVBUF, sb + KV_OFF + 6 * KVBUF};
    uint32_t sVL[2] = {sb + KV_OFF + 5 * KVBUF, sb + KV_OFF + 7 * KVBUF};

    const size_t kvbase = (size_t)b * SEQ * DIM;

#define ISSUE_K(tile, bs) do {                                             \
    const size_t _g = kvbase + (size_t)(tile) * 16 * DIM;                  \
    _Pragma("unroll")                                                      \
    for (int _i = 0; _i < 2; _i++) {                                       \
        int _idx = tid + _i * 256;                                         \
        int _row = _idx >> 5, _ch = _idx & 31;                             \
        uint32_t _d = (uint32_t)_row * RSB + _ch * 16;                     \
        size_t _go = _g + (size_t)_row * DIM + _ch * 8;                    \
        cp16(sKH[bs] + _d, g_Kh + _go);                                    \
        cp16(sKL[bs] + _d, g_Kl + _go);                                    \
    }                                                                      \
} while (0)

#define ISSUE_V(tile, bs) do {                                             \
    const size_t _g = kvbase + (size_t)(tile) * 16 * DIM;                  \
    _Pragma("unroll")                                                      \
    for (int _i = 0; _i < 2; _i++) {                                       \
        int _idx = tid + _i * 256;                                         \
        int _row = _idx >> 5, _ch = _idx & 31;                             \
        uint32_t _d = (uint32_t)_row * RSB + _ch * 16;                     \
        size_t _go = _g + (size_t)_row * DIM + _ch * 8;                    \
        cp16(sVH[bs] + _d, g_Vh + _go);                                    \
        cp16(sVL[bs] + _d, g_Vl + _go);                                    \
    }                                                                      \
} while (0)

    // prologue: {Q, K0, V0} then {K1}
    {
        const size_t qg = (size_t)(b * SEQ + q0) * DIM;
#pragma unroll
        for (int i = 0; i < 16; i++) {
            int idx = tid + i * 256;
            int row = idx >> 5, ch = idx & 31;
            uint32_t d = (uint32_t)row * RSB + ch * 16;
            size_t g = qg + (size_t)row * DIM + ch * 8;
            cp16(sQH + d, g_Qh + g);
            cp16(sQL + d, g_Ql + g);
        }
    }
    ISSUE_K(0, 0);
    ISSUE_V(0, 0);
    CP_COMMIT();
    ISSUE_K(1, 1);
    CP_COMMIT();
    CP_WAIT(1);
    __syncthreads();

    const uint32_t qoff = (uint32_t)(16 * w + (lane & 15)) * RSB + ((lane & 16) ? 16u : 0u);
    const uint32_t koff = (uint32_t)((lane & 7) + ((lane & 16) ? 8 : 0)) * RSB + ((lane & 8) ? 16u : 0u);
    const uint32_t voff = (uint32_t)((lane & 7) + ((lane & 8) ? 8 : 0)) * RSB + ((lane & 16) ? 16u : 0u);

    float oacc[32][4];
#pragma unroll
    for (int i = 0; i < 32; i++)
#pragma unroll
        for (int j = 0; j < 4; j++) oacc[i][j] = 0.f;
    float lsum0 = 0.f, lsum1 = 0.f;
    float sacc[2][4];
    uint32_t Ph[4], Pl[4];

    const float SC = 0.0625f * 1.4426950408889634f;

#define S_COMPUTE(bs) do {                                                 \
    _Pragma("unroll")                                                      \
    for (int _i = 0; _i < 2; _i++)                                         \
        _Pragma("unroll")                                                  \
        for (int _j = 0; _j < 4; _j++) sacc[_i][_j] = 0.f;                 \
    _Pragma("unroll 4")                                                    \
    for (int ks = 0; ks < 16; ks++) {                                      \
        uint32_t qh[4], ql[4], kf[4], lf[4];                               \
        ldsm_x4(qh, sQH + qoff + ks * 32);                                 \
        ldsm_x4(ql, sQL + qoff + ks * 32);                                 \
        ldsm_x4(kf, sKH[bs] + koff + ks * 32);                             \
        ldsm_x4(lf, sKL[bs] + koff + ks * 32);                             \
        _Pragma("unroll")                                                  \
        for (int h = 0; h < 2; h++) {                                      \
            mma_bf16(sacc[h], qh, &kf[2 * h]);                             \
            mma_bf16(sacc[h], qh, &lf[2 * h]);                             \
            mma_bf16(sacc[h], ql, &kf[2 * h]);                             \
        }                                                                  \
    }                                                                      \
} while (0)

#define SOFTMAX() do {                                                     \
    _Pragma("unroll")                                                      \
    for (int nt = 0; nt < 2; nt++) {                                       \
        float p0 = ex2f(sacc[nt][0] * SC);                                 \
        float p1 = ex2f(sacc[nt][1] * SC);                                 \
        float p2 = ex2f(sacc[nt][2] * SC);                                 \
        float p3 = ex2f(sacc[nt][3] * SC);                                 \
        lsum0 += p0 + p1;                                                  \
        lsum1 += p2 + p3;                                                  \
        __nv_bfloat16 h0, l0, h1, l1, h2, l2, h3, l3;                      \
        split2(p0, h0, l0); split2(p1, h1, l1);                            \
        split2(p2, h2, l2); split2(p3, h3, l3);                            \
        Ph[nt * 2]     = pack_bf(h0, h1);                                  \
        Ph[nt * 2 + 1] = pack_bf(h2, h3);                                  \
        Pl[nt * 2]     = pack_bf(l0, l1);                                  \
        Pl[nt * 2 + 1] = pack_bf(l2, l3);                                  \
    }                                                                      \
} while (0)

#define PV_ACCUM(bs) do {                                                  \
    _Pragma("unroll")                                                      \
    for (int dblk = 0; dblk < 4; dblk++)                                   \
        _Pragma("unroll")                                                  \
        for (int q = 0; q < 4; q++) {                                      \
            uint32_t vhf[4], vlf[4];                                       \
            uint32_t a = voff + (uint32_t)(dblk * 64 + q * 16) * 2;        \
            ldsm_x4_t(vhf, sVH[bs] + a);                                   \
            ldsm_x4_t(vlf, sVL[bs] + a);                                   \
            _Pragma("unroll")                                              \
            for (int h = 0; h < 2; h++) {                                  \
                const int nto = dblk * 8 + q * 2 + h;                      \
                mma_bf16(oacc[nto], Ph, &vhf[2 * h]);                      \
                mma_bf16(oacc[nto], Ph, &vlf[2 * h]);                      \
                mma_bf16(oacc[nto], Pl, &vhf[2 * h]);                      \
            }                                                              \
        }                                                                  \
} while (0)

#pragma unroll 1
    for (int t = 0; t < NT; t++) {
        const int pb = t & 1;
        // Phase A: X -> S(t); Y -> PV(t-1)
        if (grp == 0) {
            S_COMPUTE(pb);
        } else if (t > 0) {
            PV_ACCUM(pb ^ 1);
        }
        if (t == NT - 1) { CP_WAIT(0); } else { CP_WAIT(1); }
        __syncthreads();
        if (t + 1 < NT) { ISSUE_V(t + 1, pb ^ 1); CP_COMMIT(); }

        // Phase B: X -> softmax + PV(t); Y -> S(t) + softmax
        if (grp == 0) {
            SOFTMAX();
            PV_ACCUM(pb);
        } else {
            S_COMPUTE(pb);
            SOFTMAX();
        }
        CP_WAIT(1);
        __syncthreads();
        if (t + 2 < NT) { ISSUE_K(t + 2, pb); CP_COMMIT(); }
    }

    if (grp == 1) {
        PV_ACCUM((NT - 1) & 1);   // Y owes the last PV
    }

    lsum0 += __shfl_xor_sync(0xffffffffu, lsum0, 1);
    lsum0 += __shfl_xor_sync(0xffffffffu, lsum0, 2);
    lsum1 += __shfl_xor_sync(0xffffffffu, lsum1, 1);
    lsum1 += __shfl_xor_sync(0xffffffffu, lsum1, 2);
    const float inv0 = 1.0f / lsum0;
    const float inv1 = 1.0f / lsum1;

    const int r0 = q0 + 16 * w + (lane >> 2);
    const size_t base0 = ((size_t)b * SEQ + r0) * DIM + (lane & 3) * 2;
    const size_t base1 = base0 + (size_t)8 * DIM;
#pragma unroll
    for (int nto = 0; nto < 32; nto++) {
        float2 v0 = make_float2(oacc[nto][0] * inv0, oacc[nto][1] * inv0);
        float2 v1 = make_float2(oacc[nto][2] * inv1, oacc[nto][3] * inv1);
        *(float2*)&out[base0 + nto * 8] = v0;
        *(float2*)&out[base1 + nto * 8] = v1;
    }
}

// ---------------------------------------------------------------------------
extern "C" void kernel_launch(void* const* d_in, const int* in_sizes, int n_in,
                              void* d_out, int out_size)
{
    const float* x  = (const float*)d_in[0];
    const float* Wk = (const float*)d_in[1];
    const float* bk = (const float*)d_in[2];
    const float* Wq = (const float*)d_in[3];
    const float* bq = (const float*)d_in[4];
    const float* Wv = (const float*)d_in[5];
    const float* bv = (const float*)d_in[6];
    float* out = (float*)d_out;

    split_w_kernel<<<dim3(64, 3), 256>>>(Wq, Wk, Wv);

    cudaFuncSetAttribute(proj_mma, cudaFuncAttributeMaxDynamicSharedMemorySize,
                         PROJ_SMEM);
    proj_mma<<<BATCH * SEQ / 128, 256, PROJ_SMEM>>>(x, bq, bk, bv);

    cudaFuncSetAttribute(attn_mma, cudaFuncAttributeMaxDynamicSharedMemorySize,
                         ATTN_SMEM);
    attn_mma<<<dim3(SEQ / 128, BATCH), 256, ATTN_SMEM>>>(out);
}

// round 7
// speedup vs baseline: 1.6310x; 1.6310x over previous
#include <cuda_runtime.h>
#include <cuda_bf16.h>
#include <cuda_fp16.h>
#include <cstdint>

#define BATCH 4
#define SEQ   4096
#define DIM   256
#define RSB   528

// Attention operands (fp16): Q single, K split hi/lo, V single. Row-major.
static __device__ __align__(16) __half g_Q [(size_t)BATCH * SEQ * DIM];
static __device__ __align__(16) __half g_KH[(size_t)BATCH * SEQ * DIM];
static __device__ __align__(16) __half g_KL[(size_t)BATCH * SEQ * DIM];
static __device__ __align__(16) __half g_V [(size_t)BATCH * SEQ * DIM];
// Projection weights, split bf16 (proven 3-pass path)
static __device__ __align__(16) __nv_bfloat16 g_Wh[3 * DIM * DIM];
static __device__ __align__(16) __nv_bfloat16 g_Wl[3 * DIM * DIM];

// ---------------------------------------------------------------------------
__device__ __forceinline__ uint32_t smem_to_u32(const void* p) {
    uint32_t a;
    asm("{ .reg .u64 t; cvta.to.shared.u64 t, %1; cvt.u32.u64 %0, t; }"
        : "=r"(a) : "l"(p));
    return a;
}
__device__ __forceinline__ void mma_bf16(float* d, const uint32_t* a, const uint32_t* b) {
    asm volatile(
        "mma.sync.aligned.m16n8k16.row.col.f32.bf16.bf16.f32 "
        "{%0,%1,%2,%3}, {%4,%5,%6,%7}, {%8,%9}, {%0,%1,%2,%3};"
        : "+f"(d[0]), "+f"(d[1]), "+f"(d[2]), "+f"(d[3])
        : "r"(a[0]), "r"(a[1]), "r"(a[2]), "r"(a[3]), "r"(b[0]), "r"(b[1]));
}
__device__ __forceinline__ void mma_f16(float* d, const uint32_t* a, const uint32_t* b) {
    asm volatile(
        "mma.sync.aligned.m16n8k16.row.col.f32.f16.f16.f32 "
        "{%0,%1,%2,%3}, {%4,%5,%6,%7}, {%8,%9}, {%0,%1,%2,%3};"
        : "+f"(d[0]), "+f"(d[1]), "+f"(d[2]), "+f"(d[3])
        : "r"(a[0]), "r"(a[1]), "r"(a[2]), "r"(a[3]), "r"(b[0]), "r"(b[1]));
}
__device__ __forceinline__ void ldsm_x4(uint32_t* r, uint32_t addr) {
    asm volatile("ldmatrix.sync.aligned.m8n8.x4.shared.b16 {%0,%1,%2,%3}, [%4];"
        : "=r"(r[0]), "=r"(r[1]), "=r"(r[2]), "=r"(r[3]) : "r"(addr));
}
__device__ __forceinline__ void ldsm_x4_t(uint32_t* r, uint32_t addr) {
    asm volatile("ldmatrix.sync.aligned.m8n8.x4.trans.shared.b16 {%0,%1,%2,%3}, [%4];"
        : "=r"(r[0]), "=r"(r[1]), "=r"(r[2]), "=r"(r[3]) : "r"(addr));
}
__device__ __forceinline__ void cp16(uint32_t dst, const void* src) {
    asm volatile("cp.async.cg.shared.global [%0], [%1], 16;" :: "r"(dst), "l"(src));
}
#define CP_COMMIT() asm volatile("cp.async.commit_group;" ::: "memory")
#define CP_WAIT(n)  asm volatile("cp.async.wait_group %0;" :: "n"(n) : "memory")

__device__ __forceinline__ float ex2f(float x) {
    float y;
    asm("ex2.approx.ftz.f32 %0, %1;" : "=f"(y) : "f"(x));
    return y;
}
__device__ __forceinline__ uint32_t pack_bf(__nv_bfloat16 a, __nv_bfloat16 b) {
    return (uint32_t)__bfloat16_as_ushort(a) | ((uint32_t)__bfloat16_as_ushort(b) << 16);
}
__device__ __forceinline__ uint32_t pack_h(__half a, __half b) {
    return (uint32_t)__half_as_ushort(a) | ((uint32_t)__half_as_ushort(b) << 16);
}
__device__ __forceinline__ void split2(float x, __nv_bfloat16& h, __nv_bfloat16& l) {
    h = __float2bfloat16(x);
    l = __float2bfloat16(x - __bfloat162float(h));
}
__device__ __forceinline__ void split2h(float x, __half& h, __half& l) {
    h = __float2half_rn(x);
    l = __float2half_rn(x - __half2float(h));
}

// ---------------------------------------------------------------------------
// W pre-split (bf16, unchanged)
// ---------------------------------------------------------------------------
__global__ __launch_bounds__(256) void split_w_kernel(
    const float* __restrict__ Wq, const float* __restrict__ Wk,
    const float* __restrict__ Wv)
{
    const int wsel = blockIdx.y;
    const float* W = (wsel == 0) ? Wq : (wsel == 1) ? Wk : Wv;
    int idx = (blockIdx.x * 256 + threadIdx.x) * 4;
    float4 v = *(const float4*)&W[idx];
    __nv_bfloat16 h[4], l[4];
    split2(v.x, h[0], l[0]); split2(v.y, h[1], l[1]);
    split2(v.z, h[2], l[2]); split2(v.w, h[3], l[3]);
    size_t base = (size_t)wsel * DIM * DIM + idx;
    *(uint2*)&g_Wh[base] = make_uint2(pack_bf(h[0], h[1]), pack_bf(h[2], h[3]));
    *(uint2*)&g_Wl[base] = make_uint2(pack_bf(l[0], l[1]), pack_bf(l[2], l[3]));
}

// ---------------------------------------------------------------------------
// Projections: bf16 3-pass core (proven), epilogue emits fp16 Q/V + split-fp16 K
// ---------------------------------------------------------------------------
#define PXH_OFF 0
#define PXL_OFF (128 * RSB)
#define PW_OFF  (PXL_OFF + 128 * RSB)
#define PWBUF   (32 * RSB)
#define PROJ_SMEM (PW_OFF + 4 * PWBUF)

__global__ __launch_bounds__(256, 1) void proj_mma(
    const float* __restrict__ x,
    const float* __restrict__ bq, const float* __restrict__ bk,
    const float* __restrict__ bv)
{
    extern __shared__ char smem[];
    const uint32_t sb = smem_to_u32(smem);
    const int tid = threadIdx.x;
    const int lane = tid & 31;
    const int w = tid >> 5;
    const int m0 = blockIdx.x * 128;

    const uint32_t sXH = sb + PXH_OFF, sXL = sb + PXL_OFF;
    uint32_t sWH[2] = {sb + PW_OFF, sb + PW_OFF + 2 * PWBUF};
    uint32_t sWL[2] = {sb + PW_OFF + PWBUF, sb + PW_OFF + 3 * PWBUF};

#pragma unroll
    for (int i = 0; i < 4; i++) {
        int idx = tid + i * 256;
        int row = idx >> 5, c16 = idx & 31;
        uint32_t d = (uint32_t)row * RSB + c16 * 16;
        size_t g = (size_t)row * DIM + c16 * 8;
        cp16(sWH[0] + d, g_Wh + g);
        cp16(sWL[0] + d, g_Wl + g);
    }
    CP_COMMIT();

#pragma unroll
    for (int i = 0; i < 32; i++) {
        int idx = tid + i * 256;
        int row = idx >> 6, c4 = idx & 63;
        float4 v = *(const float4*)&x[(size_t)(m0 + row) * DIM + c4 * 4];
        __nv_bfloat16 h[4], l[4];
        split2(v.x, h[0], l[0]); split2(v.y, h[1], l[1]);
        split2(v.z, h[2], l[2]); split2(v.w, h[3], l[3]);
        uint32_t d = (uint32_t)row * RSB + c4 * 8;
        *(uint2*)(smem + PXH_OFF + d) = make_uint2(pack_bf(h[0], h[1]), pack_bf(h[2], h[3]));
        *(uint2*)(smem + PXL_OFF + d) = make_uint2(pack_bf(l[0], l[1]), pack_bf(l[2], l[3]));
    }

    const uint32_t aoff = (uint32_t)(16 * w + (lane & 15)) * RSB + ((lane & 16) ? 16u : 0u);
    const uint32_t boff = (uint32_t)((lane & 7) + ((lane & 8) ? 8 : 0)) * RSB + ((lane & 16) ? 16u : 0u);

    float oacc[32][4];
#pragma unroll
    for (int i = 0; i < 32; i++)
#pragma unroll
        for (int j = 0; j < 4; j++) oacc[i][j] = 0.f;

#pragma unroll 1
    for (int c = 0; c < 24; c++) {
        const int buf = c & 1;
        if (c < 23) {
            const int wsel = (c + 1) >> 3;
            const int k0 = ((c + 1) & 7) * 32;
            const size_t gbase = (size_t)wsel * DIM * DIM + (size_t)k0 * DIM;
#pragma unroll
            for (int i = 0; i < 4; i++) {
                int idx = tid + i * 256;
                int row = idx >> 5, c16 = idx & 31;
                uint32_t d = (uint32_t)row * RSB + c16 * 16;
                size_t g = gbase + (size_t)row * DIM + c16 * 8;
                cp16(sWH[buf ^ 1] + d, g_Wh + g);
                cp16(sWL[buf ^ 1] + d, g_Wl + g);
            }
            CP_COMMIT();
            CP_WAIT(1);
        } else {
            CP_WAIT(0);
        }
        __syncthreads();

        const int kbase = (c & 7) * 32;
#pragma unroll
        for (int ks = 0; ks < 2; ks++) {
            uint32_t ah[4], al[4];
            ldsm_x4(ah, sXH + aoff + (uint32_t)(kbase + ks * 16) * 2);
            ldsm_x4(al, sXL + aoff + (uint32_t)(kbase + ks * 16) * 2);
#pragma unroll
            for (int nt = 0; nt < 16; nt++) {
                uint32_t bh[4], bl[4];
                uint32_t a = (uint32_t)ks * 16 * RSB + boff + (uint32_t)nt * 32;
                ldsm_x4_t(bh, sWH[buf] + a);
                ldsm_x4_t(bl, sWL[buf] + a);
#pragma unroll
                for (int h = 0; h < 2; h++) {
                    const int nto = nt * 2 + h;
                    mma_bf16(oacc[nto], ah, &bh[2 * h]);
                    mma_bf16(oacc[nto], ah, &bl[2 * h]);
                    mma_bf16(oacc[nto], al, &bh[2 * h]);
                }
            }
        }

        if ((c & 7) == 7) {
            const int wsel = c >> 3;
            const float* bias = (wsel == 0) ? bq : (wsel == 1) ? bk : bv;
            const int r0 = m0 + 16 * w + (lane >> 2);
            const size_t base0 = (size_t)r0 * DIM + (lane & 3) * 2;
            const size_t base1 = base0 + (size_t)8 * DIM;
#pragma unroll
            for (int nto = 0; nto < 32; nto++) {
                const int col = nto * 8 + (lane & 3) * 2;
                float b0 = bias[col], b1 = bias[col + 1];
                float v00 = oacc[nto][0] + b0, v01 = oacc[nto][1] + b1;
                float v10 = oacc[nto][2] + b0, v11 = oacc[nto][3] + b1;
                if (wsel == 1) {      // K: split fp16
                    __half h0, l0, h1, l1;
                    split2h(v00, h0, l0); split2h(v01, h1, l1);
                    *(uint32_t*)&g_KH[base0 + nto * 8] = pack_h(h0, h1);
                    *(uint32_t*)&g_KL[base0 + nto * 8] = pack_h(l0, l1);
                    split2h(v10, h0, l0); split2h(v11, h1, l1);
                    *(uint32_t*)&g_KH[base1 + nto * 8] = pack_h(h0, h1);
                    *(uint32_t*)&g_KL[base1 + nto * 8] = pack_h(l0, l1);
                } else {              // Q or V: single fp16
                    __half* dst = (wsel == 0) ? g_Q : g_V;
                    *(uint32_t*)&dst[base0 + nto * 8] =
                        pack_h(__float2half_rn(v00), __float2half_rn(v01));
                    *(uint32_t*)&dst[base1 + nto * 8] =
                        pack_h(__float2half_rn(v10), __float2half_rn(v11));
                }
                oacc[nto][0] = oacc[nto][1] = oacc[nto][2] = oacc[nto][3] = 0.f;
            }
        }
        __syncthreads();
    }
}

// ---------------------------------------------------------------------------
// Attention, fp16 asymmetric splits: S = Q.(Kh+Kl), O = (Ph+Pl).V
// 32-key tiles, triple-buffered {KH,KL,V}, ONE syncthreads per tile.
// SMEM: Q 67584 + 3 * (3 * 16896) = 219648 bytes.
// ---------------------------------------------------------------------------
#define AQ_OFF   0
#define ABUF_OFF (128 * RSB)            // 67584
#define ABUF_STR (3 * 32 * RSB)         // 50688 per tile-buffer (KH|KL|V)
#define ATTN_SMEM (ABUF_OFF + 3 * ABUF_STR)  // 219648
#define NKT 128

__global__ __launch_bounds__(256, 1) void attn_mma(float* __restrict__ out)
{
    extern __shared__ char smem[];
    const uint32_t sb = smem_to_u32(smem);
    const int tid = threadIdx.x;
    const int lane = tid & 31;
    const int w = tid >> 5;
    const int b = blockIdx.y;
    const int q0 = blockIdx.x * 128;

    const uint32_t sQ = sb + AQ_OFF;
    const size_t kvbase = (size_t)b * SEQ * DIM;

#define ISSUE_TILE(tile, bs) do {                                          \
    const size_t _g = kvbase + (size_t)(tile) * 32 * DIM;                  \
    const uint32_t _bb = sb + ABUF_OFF + (uint32_t)(bs) * ABUF_STR;        \
    _Pragma("unroll")                                                      \
    for (int _i = 0; _i < 4; _i++) {                                       \
        int _idx = tid + _i * 256;                                         \
        int _row = _idx >> 5, _ch = _idx & 31;                             \
        uint32_t _d = (uint32_t)_row * RSB + _ch * 16;                     \
        size_t _go = _g + (size_t)_row * DIM + _ch * 8;                    \
        cp16(_bb + _d, g_KH + _go);                                        \
        cp16(_bb + 32 * RSB + _d, g_KL + _go);                             \
        cp16(_bb + 64 * RSB + _d, g_V + _go);                              \
    }                                                                      \
} while (0)

    // prologue: group A = {Q, tile0}; group B = {tile1}
    {
        const size_t qg = (size_t)(b * SEQ + q0) * DIM;
#pragma unroll
        for (int i = 0; i < 16; i++) {
            int idx = tid + i * 256;
            int row = idx >> 5, ch = idx & 31;
            uint32_t d = (uint32_t)row * RSB + ch * 16;
            cp16(sQ + d, g_Q + qg + (size_t)row * DIM + ch * 8);
        }
    }
    ISSUE_TILE(0, 0);
    CP_COMMIT();
    ISSUE_TILE(1, 1);
    CP_COMMIT();

    const uint32_t qoff = (uint32_t)(16 * w + (lane & 15)) * RSB + ((lane & 16) ? 16u : 0u);
    const uint32_t koff = (uint32_t)((lane & 7) + ((lane & 16) ? 8 : 0)) * RSB + ((lane & 8) ? 16u : 0u);
    const uint32_t voff = (uint32_t)((lane & 7) + ((lane & 8) ? 8 : 0)) * RSB + ((lane & 16) ? 16u : 0u);

    float oacc[32][4];
#pragma unroll
    for (int i = 0; i < 32; i++)
#pragma unroll
        for (int j = 0; j < 4; j++) oacc[i][j] = 0.f;
    float lsum0 = 0.f, lsum1 = 0.f;

    const float SC = 0.0625f * 1.4426950408889634f;

    int cb = 0;        // buffer of tile t
    int ib = 2;        // buffer for tile t+2

#pragma unroll 1
    for (int t = 0; t < NKT; t++) {
        if (t < NKT - 1) { CP_WAIT(1); } else { CP_WAIT(0); }
        __syncthreads();                       // buf(t) ready; prev reads done
        if (t + 2 < NKT) { ISSUE_TILE(t + 2, ib); CP_COMMIT(); }

        const uint32_t bKH = sb + ABUF_OFF + (uint32_t)cb * ABUF_STR;
        const uint32_t bKL = bKH + 32 * RSB;
        const uint32_t bV  = bKH + 64 * RSB;

        // ---- S = Q . (Kh + Kl)^T : 8 mmas/kstep ----
        float sacc[4][4];
#pragma unroll
        for (int i = 0; i < 4; i++)
#pragma unroll
            for (int j = 0; j < 4; j++) sacc[i][j] = 0.f;

#pragma unroll 4
        for (int ks = 0; ks < 16; ks++) {
            uint32_t qf[4], kh[2][4], kl[2][4];
            ldsm_x4(qf, sQ + qoff + ks * 32);
#pragma unroll
            for (int np = 0; np < 2; np++) {
                ldsm_x4(kh[np], bKH + koff + (uint32_t)np * 16 * RSB + ks * 32);
                ldsm_x4(kl[np], bKL + koff + (uint32_t)np * 16 * RSB + ks * 32);
            }
#pragma unroll
            for (int np = 0; np < 2; np++)
#pragma unroll
                for (int h = 0; h < 2; h++) {
                    const int nt = np * 2 + h;
                    mma_f16(sacc[nt], qf, &kh[np][2 * h]);
                    mma_f16(sacc[nt], qf, &kl[np][2 * h]);
                }
        }

        // ---- softmax, P split to fp16 pairs ----
        uint32_t Ph[2][4], Pl[2][4];
#pragma unroll
        for (int nt = 0; nt < 4; nt++) {
            float p0 = ex2f(sacc[nt][0] * SC);
            float p1 = ex2f(sacc[nt][1] * SC);
            float p2 = ex2f(sacc[nt][2] * SC);
            float p3 = ex2f(sacc[nt][3] * SC);
            lsum0 += p0 + p1;
            lsum1 += p2 + p3;
            __half h0, l0, h1, l1, h2, l2, h3, l3;
            split2h(p0, h0, l0); split2h(p1, h1, l1);
            split2h(p2, h2, l2); split2h(p3, h3, l3);
            const int j = nt >> 1, bs = (nt & 1) * 2;
            Ph[j][bs]     = pack_h(h0, h1);
            Ph[j][bs + 1] = pack_h(h2, h3);
            Pl[j][bs]     = pack_h(l0, l1);
            Pl[j][bs + 1] = pack_h(l2, l3);
        }

        // ---- O += (Ph + Pl) . V : 4 mmas per (dblk,kc,q) pair-half ----
#pragma unroll
        for (int dblk = 0; dblk < 4; dblk++)
#pragma unroll
            for (int kc = 0; kc < 2; kc++) {
#pragma unroll
                for (int q = 0; q < 4; q++) {
                    uint32_t vf[4];
                    uint32_t a = (uint32_t)kc * 16 * RSB + voff + (uint32_t)(dblk * 64 + q * 16) * 2;
                    ldsm_x4_t(vf, bV + a);
#pragma unroll
                    for (int h = 0; h < 2; h++) {
                        const int nto = dblk * 8 + q * 2 + h;
                        mma_f16(oacc[nto], Ph[kc], &vf[2 * h]);
                        mma_f16(oacc[nto], Pl[kc], &vf[2 * h]);
                    }
                }
            }

        cb = (cb == 2) ? 0 : cb + 1;
        ib = (ib == 2) ? 0 : ib + 1;
    }

    // ---- epilogue ----
    lsum0 += __shfl_xor_sync(0xffffffffu, lsum0, 1);
    lsum0 += __shfl_xor_sync(0xffffffffu, lsum0, 2);
    lsum1 += __shfl_xor_sync(0xffffffffu, lsum1, 1);
    lsum1 += __shfl_xor_sync(0xffffffffu, lsum1, 2);
    const float inv0 = 1.0f / lsum0;
    const float inv1 = 1.0f / lsum1;

    const int r0 = q0 + 16 * w + (lane >> 2);
    const size_t base0 = ((size_t)b * SEQ + r0) * DIM + (lane & 3) * 2;
    const size_t base1 = base0 + (size_t)8 * DIM;
#pragma unroll
    for (int nto = 0; nto < 32; nto++) {
        float2 v0 = make_float2(oacc[nto][0] * inv0, oacc[nto][1] * inv0);
        float2 v1 = make_float2(oacc[nto][2] * inv1, oacc[nto][3] * inv1);
        *(float2*)&out[base0 + nto * 8] = v0;
        *(float2*)&out[base1 + nto * 8] = v1;
    }
}

// ---------------------------------------------------------------------------
extern "C" void kernel_launch(void* const* d_in, const int* in_sizes, int n_in,
                              void* d_out, int out_size)
{
    const float* x  = (const float*)d_in[0];
    const float* Wk = (const float*)d_in[1];
    const float* bk = (const float*)d_in[2];
    const float* Wq = (const float*)d_in[3];
    const float* bq = (const float*)d_in[4];
    const float* Wv = (const float*)d_in[5];
    const float* bv = (const float*)d_in[6];
    float* out = (float*)d_out;

    split_w_kernel<<<dim3(64, 3), 256>>>(Wq, Wk, Wv);

    cudaFuncSetAttribute(proj_mma, cudaFuncAttributeMaxDynamicSharedMemorySize,
                         PROJ_SMEM);
    proj_mma<<<BATCH * SEQ / 128, 256, PROJ_SMEM>>>(x, bq, bk, bv);

    cudaFuncSetAttribute(attn_mma, cudaFuncAttributeMaxDynamicSharedMemorySize,
                         ATTN_SMEM);
    attn_mma<<<dim3(SEQ / 128, BATCH), 256, ATTN_SMEM>>>(out);
}

// round 8
// speedup vs baseline: 2.4063x; 1.4753x over previous
#include <cuda_runtime.h>
#include <cuda_bf16.h>
#include <cuda_fp16.h>
#include <cstdint>

#define BATCH 4
#define SEQ   4096
#define DIM   256
#define RSB   528

// Attention operands: plain fp16, row-major
static __device__ __align__(16) __half g_Q[(size_t)BATCH * SEQ * DIM];
static __device__ __align__(16) __half g_K[(size_t)BATCH * SEQ * DIM];
static __device__ __align__(16) __half g_V[(size_t)BATCH * SEQ * DIM];
// Projection weights, split bf16 (proven 3-pass path)
static __device__ __align__(16) __nv_bfloat16 g_Wh[3 * DIM * DIM];
static __device__ __align__(16) __nv_bfloat16 g_Wl[3 * DIM * DIM];

// ---------------------------------------------------------------------------
__device__ __forceinline__ uint32_t smem_to_u32(const void* p) {
    uint32_t a;
    asm("{ .reg .u64 t; cvta.to.shared.u64 t, %1; cvt.u32.u64 %0, t; }"
        : "=r"(a) : "l"(p));
    return a;
}
__device__ __forceinline__ void mma_bf16(float* d, const uint32_t* a, const uint32_t* b) {
    asm volatile(
        "mma.sync.aligned.m16n8k16.row.col.f32.bf16.bf16.f32 "
        "{%0,%1,%2,%3}, {%4,%5,%6,%7}, {%8,%9}, {%0,%1,%2,%3};"
        : "+f"(d[0]), "+f"(d[1]), "+f"(d[2]), "+f"(d[3])
        : "r"(a[0]), "r"(a[1]), "r"(a[2]), "r"(a[3]), "r"(b[0]), "r"(b[1]));
}
__device__ __forceinline__ void mma_f16(float* d, const uint32_t* a, const uint32_t* b) {
    asm volatile(
        "mma.sync.aligned.m16n8k16.row.col.f32.f16.f16.f32 "
        "{%0,%1,%2,%3}, {%4,%5,%6,%7}, {%8,%9}, {%0,%1,%2,%3};"
        : "+f"(d[0]), "+f"(d[1]), "+f"(d[2]), "+f"(d[3])
        : "r"(a[0]), "r"(a[1]), "r"(a[2]), "r"(a[3]), "r"(b[0]), "r"(b[1]));
}
__device__ __forceinline__ void ldsm_x4(uint32_t* r, uint32_t addr) {
    asm volatile("ldmatrix.sync.aligned.m8n8.x4.shared.b16 {%0,%1,%2,%3}, [%4];"
        : "=r"(r[0]), "=r"(r[1]), "=r"(r[2]), "=r"(r[3]) : "r"(addr));
}
__device__ __forceinline__ void ldsm_x4_t(uint32_t* r, uint32_t addr) {
    asm volatile("ldmatrix.sync.aligned.m8n8.x4.trans.shared.b16 {%0,%1,%2,%3}, [%4];"
        : "=r"(r[0]), "=r"(r[1]), "=r"(r[2]), "=r"(r[3]) : "r"(addr));
}
__device__ __forceinline__ void cp16(uint32_t dst, const void* src) {
    asm volatile("cp.async.cg.shared.global [%0], [%1], 16;" :: "r"(dst), "l"(src));
}
#define CP_COMMIT() asm volatile("cp.async.commit_group;" ::: "memory")
#define CP_WAIT(n)  asm volatile("cp.async.wait_group %0;" :: "n"(n) : "memory")

__device__ __forceinline__ float ex2f(float x) {
    float y;
    asm("ex2.approx.ftz.f32 %0, %1;" : "=f"(y) : "f"(x));
    return y;
}
__device__ __forceinline__ uint32_t pack_bf(__nv_bfloat16 a, __nv_bfloat16 b) {
    return (uint32_t)__bfloat16_as_ushort(a) | ((uint32_t)__bfloat16_as_ushort(b) << 16);
}
__device__ __forceinline__ uint32_t pack_h(__half a, __half b) {
    return (uint32_t)__half_as_ushort(a) | ((uint32_t)__half_as_ushort(b) << 16);
}
__device__ __forceinline__ void split2(float x, __nv_bfloat16& h, __nv_bfloat16& l) {
    h = __float2bfloat16(x);
    l = __float2bfloat16(x - __bfloat162float(h));
}

// ---------------------------------------------------------------------------
// W pre-split (bf16, unchanged)
// ---------------------------------------------------------------------------
__global__ __launch_bounds__(256) void split_w_kernel(
    const float* __restrict__ Wq, const float* __restrict__ Wk,
    const float* __restrict__ Wv)
{
    const int wsel = blockIdx.y;
    const float* W = (wsel == 0) ? Wq : (wsel == 1) ? Wk : Wv;
    int idx = (blockIdx.x * 256 + threadIdx.x) * 4;
    float4 v = *(const float4*)&W[idx];
    __nv_bfloat16 h[4], l[4];
    split2(v.x, h[0], l[0]); split2(v.y, h[1], l[1]);
    split2(v.z, h[2], l[2]); split2(v.w, h[3], l[3]);
    size_t base = (size_t)wsel * DIM * DIM + idx;
    *(uint2*)&g_Wh[base] = make_uint2(pack_bf(h[0], h[1]), pack_bf(h[2], h[3]));
    *(uint2*)&g_Wl[base] = make_uint2(pack_bf(l[0], l[1]), pack_bf(l[2], l[3]));
}

// ---------------------------------------------------------------------------
// Projections: bf16 3-pass core (proven), epilogue emits fp16 Q/K/V
// ---------------------------------------------------------------------------
#define PXH_OFF 0
#define PXL_OFF (128 * RSB)
#define PW_OFF  (PXL_OFF + 128 * RSB)
#define PWBUF   (32 * RSB)
#define PROJ_SMEM (PW_OFF + 4 * PWBUF)

__global__ __launch_bounds__(256, 1) void proj_mma(
    const float* __restrict__ x,
    const float* __restrict__ bq, const float* __restrict__ bk,
    const float* __restrict__ bv)
{
    extern __shared__ char smem[];
    const uint32_t sb = smem_to_u32(smem);
    const int tid = threadIdx.x;
    const int lane = tid & 31;
    const int w = tid >> 5;
    const int m0 = blockIdx.x * 128;

    const uint32_t sXH = sb + PXH_OFF, sXL = sb + PXL_OFF;
    uint32_t sWH[2] = {sb + PW_OFF, sb + PW_OFF + 2 * PWBUF};
    uint32_t sWL[2] = {sb + PW_OFF + PWBUF, sb + PW_OFF + 3 * PWBUF};

#pragma unroll
    for (int i = 0; i < 4; i++) {
        int idx = tid + i * 256;
        int row = idx >> 5, c16 = idx & 31;
        uint32_t d = (uint32_t)row * RSB + c16 * 16;
        size_t g = (size_t)row * DIM + c16 * 8;
        cp16(sWH[0] + d, g_Wh + g);
        cp16(sWL[0] + d, g_Wl + g);
    }
    CP_COMMIT();

#pragma unroll
    for (int i = 0; i < 32; i++) {
        int idx = tid + i * 256;
        int row = idx >> 6, c4 = idx & 63;
        float4 v = *(const float4*)&x[(size_t)(m0 + row) * DIM + c4 * 4];
        __nv_bfloat16 h[4], l[4];
        split2(v.x, h[0], l[0]); split2(v.y, h[1], l[1]);
        split2(v.z, h[2], l[2]); split2(v.w, h[3], l[3]);
        uint32_t d = (uint32_t)row * RSB + c4 * 8;
        *(uint2*)(smem + PXH_OFF + d) = make_uint2(pack_bf(h[0], h[1]), pack_bf(h[2], h[3]));
        *(uint2*)(smem + PXL_OFF + d) = make_uint2(pack_bf(l[0], l[1]), pack_bf(l[2], l[3]));
    }

    const uint32_t aoff = (uint32_t)(16 * w + (lane & 15)) * RSB + ((lane & 16) ? 16u : 0u);
    const uint32_t boff = (uint32_t)((lane & 7) + ((lane & 8) ? 8 : 0)) * RSB + ((lane & 16) ? 16u : 0u);

    float oacc[32][4];
#pragma unroll
    for (int i = 0; i < 32; i++)
#pragma unroll
        for (int j = 0; j < 4; j++) oacc[i][j] = 0.f;

#pragma unroll 1
    for (int c = 0; c < 24; c++) {
        const int buf = c & 1;
        if (c < 23) {
            const int wsel = (c + 1) >> 3;
            const int k0 = ((c + 1) & 7) * 32;
            const size_t gbase = (size_t)wsel * DIM * DIM + (size_t)k0 * DIM;
#pragma unroll
            for (int i = 0; i < 4; i++) {
                int idx = tid + i * 256;
                int row = idx >> 5, c16 = idx & 31;
                uint32_t d = (uint32_t)row * RSB + c16 * 16;
                size_t g = gbase + (size_t)row * DIM + c16 * 8;
                cp16(sWH[buf ^ 1] + d, g_Wh + g);
                cp16(sWL[buf ^ 1] + d, g_Wl + g);
            }
            CP_COMMIT();
            CP_WAIT(1);
        } else {
            CP_WAIT(0);
        }
        __syncthreads();

        const int kbase = (c & 7) * 32;
#pragma unroll
        for (int ks = 0; ks < 2; ks++) {
            uint32_t ah[4], al[4];
            ldsm_x4(ah, sXH + aoff + (uint32_t)(kbase + ks * 16) * 2);
            ldsm_x4(al, sXL + aoff + (uint32_t)(kbase + ks * 16) * 2);
#pragma unroll
            for (int nt = 0; nt < 16; nt++) {
                uint32_t bh[4], bl[4];
                uint32_t a = (uint32_t)ks * 16 * RSB + boff + (uint32_t)nt * 32;
                ldsm_x4_t(bh, sWH[buf] + a);
                ldsm_x4_t(bl, sWL[buf] + a);
#pragma unroll
                for (int h = 0; h < 2; h++) {
                    const int nto = nt * 2 + h;
                    mma_bf16(oacc[nto], ah, &bh[2 * h]);
                    mma_bf16(oacc[nto], ah, &bl[2 * h]);
                    mma_bf16(oacc[nto], al, &bh[2 * h]);
                }
            }
        }

        if ((c & 7) == 7) {
            const int wsel = c >> 3;
            const float* bias = (wsel == 0) ? bq : (wsel == 1) ? bk : bv;
            __half* dst = (wsel == 0) ? g_Q : (wsel == 1) ? g_K : g_V;
            const int r0 = m0 + 16 * w + (lane >> 2);
            const size_t base0 = (size_t)r0 * DIM + (lane & 3) * 2;
            const size_t base1 = base0 + (size_t)8 * DIM;
#pragma unroll
            for (int nto = 0; nto < 32; nto++) {
                const int col = nto * 8 + (lane & 3) * 2;
                float b0 = bias[col], b1 = bias[col + 1];
                *(uint32_t*)&dst[base0 + nto * 8] =
                    pack_h(__float2half_rn(oacc[nto][0] + b0),
                           __float2half_rn(oacc[nto][1] + b1));
                *(uint32_t*)&dst[base1 + nto * 8] =
                    pack_h(__float2half_rn(oacc[nto][2] + b0),
                           __float2half_rn(oacc[nto][3] + b1));
                oacc[nto][0] = oacc[nto][1] = oacc[nto][2] = oacc[nto][3] = 0.f;
            }
        }
        __syncthreads();
    }
}

// ---------------------------------------------------------------------------
// Attention, plain fp16 mma: S = Q.K^T, O = P.V  (single pass each)
// 32-key tiles, triple-buffered {K,V}, one syncthreads per tile.
// SMEM: Q 67584 + 3 * (2 * 16896) = 168960 bytes.
// ---------------------------------------------------------------------------
#define AQ_OFF   0
#define ABUF_OFF (128 * RSB)            // 67584
#define ABUF_STR (2 * 32 * RSB)         // 33792 per tile-buffer (K|V)
#define ATTN_SMEM (ABUF_OFF + 3 * ABUF_STR)  // 168960
#define NKT 128

__global__ __launch_bounds__(256, 1) void attn_mma(float* __restrict__ out)
{
    extern __shared__ char smem[];
    const uint32_t sb = smem_to_u32(smem);
    const int tid = threadIdx.x;
    const int lane = tid & 31;
    const int w = tid >> 5;
    const int b = blockIdx.y;
    const int q0 = blockIdx.x * 128;

    const uint32_t sQ = sb + AQ_OFF;
    const size_t kvbase = (size_t)b * SEQ * DIM;

#define ISSUE_TILE(tile, bs) do {                                          \
    const size_t _g = kvbase + (size_t)(tile) * 32 * DIM;                  \
    const uint32_t _bb = sb + ABUF_OFF + (uint32_t)(bs) * ABUF_STR;        \
    _Pragma("unroll")                                                      \
    for (int _i = 0; _i < 4; _i++) {                                       \
        int _idx = tid + _i * 256;                                         \
        int _row = _idx >> 5, _ch = _idx & 31;                             \
        uint32_t _d = (uint32_t)_row * RSB + _ch * 16;                     \
        size_t _go = _g + (size_t)_row * DIM + _ch * 8;                    \
        cp16(_bb + _d, g_K + _go);                                         \
        cp16(_bb + 32 * RSB + _d, g_V + _go);                              \
    }                                                                      \
} while (0)

    // prologue
    {
        const size_t qg = (size_t)(b * SEQ + q0) * DIM;
#pragma unroll
        for (int i = 0; i < 16; i++) {
            int idx = tid + i * 256;
            int row = idx >> 5, ch = idx & 31;
            uint32_t d = (uint32_t)row * RSB + ch * 16;
            cp16(sQ + d, g_Q + qg + (size_t)row * DIM + ch * 8);
        }
    }
    ISSUE_TILE(0, 0);
    CP_COMMIT();
    ISSUE_TILE(1, 1);
    CP_COMMIT();

    const uint32_t qoff = (uint32_t)(16 * w + (lane & 15)) * RSB + ((lane & 16) ? 16u : 0u);
    const uint32_t koff = (uint32_t)((lane & 7) + ((lane & 16) ? 8 : 0)) * RSB + ((lane & 8) ? 16u : 0u);
    const uint32_t voff = (uint32_t)((lane & 7) + ((lane & 8) ? 8 : 0)) * RSB + ((lane & 16) ? 16u : 0u);

    float oacc[32][4];
#pragma unroll
    for (int i = 0; i < 32; i++)
#pragma unroll
        for (int j = 0; j < 4; j++) oacc[i][j] = 0.f;
    float lsum0 = 0.f, lsum1 = 0.f;

    const float SC = 0.0625f * 1.4426950408889634f;

    int cb = 0, ib = 2;

#pragma unroll 1
    for (int t = 0; t < NKT; t++) {
        if (t < NKT - 1) { CP_WAIT(1); } else { CP_WAIT(0); }
        __syncthreads();
        if (t + 2 < NKT) { ISSUE_TILE(t + 2, ib); CP_COMMIT(); }

        const uint32_t bK = sb + ABUF_OFF + (uint32_t)cb * ABUF_STR;
        const uint32_t bV = bK + 32 * RSB;

        // ---- S = Q . K^T : 4 mmas/kstep ----
        float sacc[4][4];
#pragma unroll
        for (int i = 0; i < 4; i++)
#pragma unroll
            for (int j = 0; j < 4; j++) sacc[i][j] = 0.f;

#pragma unroll 4
        for (int ks = 0; ks < 16; ks++) {
            uint32_t qf[4], kf[2][4];
            ldsm_x4(qf, sQ + qoff + ks * 32);
#pragma unroll
            for (int np = 0; np < 2; np++)
                ldsm_x4(kf[np], bK + koff + (uint32_t)np * 16 * RSB + ks * 32);
#pragma unroll
            for (int np = 0; np < 2; np++)
#pragma unroll
                for (int h = 0; h < 2; h++)
                    mma_f16(sacc[np * 2 + h], qf, &kf[np][2 * h]);
        }

        // ---- softmax, P -> fp16 ----
        uint32_t Pf[2][4];
#pragma unroll
        for (int nt = 0; nt < 4; nt++) {
            float p0 = ex2f(sacc[nt][0] * SC);
            float p1 = ex2f(sacc[nt][1] * SC);
            float p2 = ex2f(sacc[nt][2] * SC);
            float p3 = ex2f(sacc[nt][3] * SC);
            lsum0 += p0 + p1;
            lsum1 += p2 + p3;
            const int j = nt >> 1, bs = (nt & 1) * 2;
            Pf[j][bs]     = pack_h(__float2half_rn(p0), __float2half_rn(p1));
            Pf[j][bs + 1] = pack_h(__float2half_rn(p2), __float2half_rn(p3));
        }

        // ---- O += P . V ----
#pragma unroll
        for (int dblk = 0; dblk < 4; dblk++)
#pragma unroll
            for (int kc = 0; kc < 2; kc++) {
#pragma unroll
                for (int q = 0; q < 4; q++) {
                    uint32_t vf[4];
                    uint32_t a = (uint32_t)kc * 16 * RSB + voff + (uint32_t)(dblk * 64 + q * 16) * 2;
                    ldsm_x4_t(vf, bV + a);
#pragma unroll
                    for (int h = 0; h < 2; h++)
                        mma_f16(oacc[dblk * 8 + q * 2 + h], Pf[kc], &vf[2 * h]);
                }
            }

        cb = (cb == 2) ? 0 : cb + 1;
        ib = (ib == 2) ? 0 : ib + 1;
    }

    // ---- epilogue ----
    lsum0 += __shfl_xor_sync(0xffffffffu, lsum0, 1);
    lsum0 += __shfl_xor_sync(0xffffffffu, lsum0, 2);
    lsum1 += __shfl_xor_sync(0xffffffffu, lsum1, 1);
    lsum1 += __shfl_xor_sync(0xffffffffu, lsum1, 2);
    const float inv0 = 1.0f / lsum0;
    const float inv1 = 1.0f / lsum1;

    const int r0 = q0 + 16 * w + (lane >> 2);
    const size_t base0 = ((size_t)b * SEQ + r0) * DIM + (lane & 3) * 2;
    const size_t base1 = base0 + (size_t)8 * DIM;
#pragma unroll
    for (int nto = 0; nto < 32; nto++) {
        float2 v0 = make_float2(oacc[nto][0] * inv0, oacc[nto][1] * inv0);
        float2 v1 = make_float2(oacc[nto][2] * inv1, oacc[nto][3] * inv1);
        *(float2*)&out[base0 + nto * 8] = v0;
        *(float2*)&out[base1 + nto * 8] = v1;
    }
}

// ---------------------------------------------------------------------------
extern "C" void kernel_launch(void* const* d_in, const int* in_sizes, int n_in,
                              void* d_out, int out_size)
{
    const float* x  = (const float*)d_in[0];
    const float* Wk = (const float*)d_in[1];
    const float* bk = (const float*)d_in[2];
    const float* Wq = (const float*)d_in[3];
    const float* bq = (const float*)d_in[4];
    const float* Wv = (const float*)d_in[5];
    const float* bv = (const float*)d_in[6];
    float* out = (float*)d_out;

    split_w_kernel<<<dim3(64, 3), 256>>>(Wq, Wk, Wv);

    cudaFuncSetAttribute(proj_mma, cudaFuncAttributeMaxDynamicSharedMemorySize,
                         PROJ_SMEM);
    proj_mma<<<BATCH * SEQ / 128, 256, PROJ_SMEM>>>(x, bq, bk, bv);

    cudaFuncSetAttribute(attn_mma, cudaFuncAttributeMaxDynamicSharedMemorySize,
                         ATTN_SMEM);
    attn_mma<<<dim3(SEQ / 128, BATCH), 256, ATTN_SMEM>>>(out);
}

// round 9
// speedup vs baseline: 2.6533x; 1.1027x over previous
#include <cuda_runtime.h>
#include <cuda_fp16.h>
#include <cstdint>

#define BATCH 4
#define SEQ   4096
#define DIM   256
#define RSB   528

// Attention operands: plain fp16, row-major
static __device__ __align__(16) __half g_Q[(size_t)BATCH * SEQ * DIM];
static __device__ __align__(16) __half g_K[(size_t)BATCH * SEQ * DIM];
static __device__ __align__(16) __half g_V[(size_t)BATCH * SEQ * DIM];
// Projection weights, fp16: [3][256*256] (0=Wq, 1=Wk, 2=Wv)
static __device__ __align__(16) __half g_W16[3 * DIM * DIM];

// ---------------------------------------------------------------------------
__device__ __forceinline__ uint32_t smem_to_u32(const void* p) {
    uint32_t a;
    asm("{ .reg .u64 t; cvta.to.shared.u64 t, %1; cvt.u32.u64 %0, t; }"
        : "=r"(a) : "l"(p));
    return a;
}
__device__ __forceinline__ void mma_f16(float* d, const uint32_t* a, const uint32_t* b) {
    asm volatile(
        "mma.sync.aligned.m16n8k16.row.col.f32.f16.f16.f32 "
        "{%0,%1,%2,%3}, {%4,%5,%6,%7}, {%8,%9}, {%0,%1,%2,%3};"
        : "+f"(d[0]), "+f"(d[1]), "+f"(d[2]), "+f"(d[3])
        : "r"(a[0]), "r"(a[1]), "r"(a[2]), "r"(a[3]), "r"(b[0]), "r"(b[1]));
}
__device__ __forceinline__ void ldsm_x4(uint32_t* r, uint32_t addr) {
    asm volatile("ldmatrix.sync.aligned.m8n8.x4.shared.b16 {%0,%1,%2,%3}, [%4];"
        : "=r"(r[0]), "=r"(r[1]), "=r"(r[2]), "=r"(r[3]) : "r"(addr));
}
__device__ __forceinline__ void ldsm_x4_t(uint32_t* r, uint32_t addr) {
    asm volatile("ldmatrix.sync.aligned.m8n8.x4.trans.shared.b16 {%0,%1,%2,%3}, [%4];"
        : "=r"(r[0]), "=r"(r[1]), "=r"(r[2]), "=r"(r[3]) : "r"(addr));
}
__device__ __forceinline__ void cp16(uint32_t dst, const void* src) {
    asm volatile("cp.async.cg.shared.global [%0], [%1], 16;" :: "r"(dst), "l"(src));
}
#define CP_COMMIT() asm volatile("cp.async.commit_group;" ::: "memory")
#define CP_WAIT(n)  asm volatile("cp.async.wait_group %0;" :: "n"(n) : "memory")

__device__ __forceinline__ float ex2f(float x) {
    float y;
    asm("ex2.approx.ftz.f32 %0, %1;" : "=f"(y) : "f"(x));
    return y;
}
__device__ __forceinline__ uint32_t pack_h(__half a, __half b) {
    return (uint32_t)__half_as_ushort(a) | ((uint32_t)__half_as_ushort(b) << 16);
}

// ---------------------------------------------------------------------------
// W convert: 3 x 256x256 fp32 -> fp16
// ---------------------------------------------------------------------------
__global__ __launch_bounds__(256) void conv_w_kernel(
    const float* __restrict__ Wq, const float* __restrict__ Wk,
    const float* __restrict__ Wv)
{
    const int wsel = blockIdx.y;
    const float* W = (wsel == 0) ? Wq : (wsel == 1) ? Wk : Wv;
    int idx = (blockIdx.x * 256 + threadIdx.x) * 4;
    float4 v = *(const float4*)&W[idx];
    size_t base = (size_t)wsel * DIM * DIM + idx;
    *(uint2*)&g_W16[base] = make_uint2(
        pack_h(__float2half_rn(v.x), __float2half_rn(v.y)),
        pack_h(__float2half_rn(v.z), __float2half_rn(v.w)));
}

// ---------------------------------------------------------------------------
// Single-pass fp16 projections: Q/K/V = x @ W + b.
// CTA = 128 rows of x (fp16, resident). W streamed in 64-k-row chunks,
// double-buffered. 12 chunks total (4 per weight); epilogue per weight.
// SMEM: x 67584 + 2 * 33792 = 135168 bytes.
// ---------------------------------------------------------------------------
#define PX_OFF  0
#define PW_OFF  (128 * RSB)                 // 67584
#define PWBUF   (64 * RSB)                  // 33792
#define PROJ_SMEM (PW_OFF + 2 * PWBUF)      // 135168

__global__ __launch_bounds__(256, 1) void proj_mma(
    const float* __restrict__ x,
    const float* __restrict__ bq, const float* __restrict__ bk,
    const float* __restrict__ bv)
{
    extern __shared__ char smem[];
    const uint32_t sb = smem_to_u32(smem);
    const int tid = threadIdx.x;
    const int lane = tid & 31;
    const int w = tid >> 5;
    const int m0 = blockIdx.x * 128;

    const uint32_t sX = sb + PX_OFF;
    uint32_t sW[2] = {sb + PW_OFF, sb + PW_OFF + PWBUF};

    // ---- prefetch W chunk 0 (wsel=0, k rows 0..63) ----
#pragma unroll
    for (int i = 0; i < 8; i++) {
        int idx = tid + i * 256;            // 2048 16B-lines
        int row = idx >> 5, c16 = idx & 31;
        uint32_t d = (uint32_t)row * RSB + c16 * 16;
        cp16(sW[0] + d, g_W16 + (size_t)row * DIM + c16 * 8);
    }
    CP_COMMIT();

    // ---- load + convert resident x tile (fp32 -> fp16) ----
#pragma unroll
    for (int i = 0; i < 32; i++) {
        int idx = tid + i * 256;            // 8192 float4
        int row = idx >> 6, c4 = idx & 63;
        float4 v = *(const float4*)&x[(size_t)(m0 + row) * DIM + c4 * 4];
        uint32_t d = (uint32_t)row * RSB + c4 * 8;
        *(uint2*)(smem + PX_OFF + d) = make_uint2(
            pack_h(__float2half_rn(v.x), __float2half_rn(v.y)),
            pack_h(__float2half_rn(v.z), __float2half_rn(v.w)));
    }

    const uint32_t aoff = (uint32_t)(16 * w + (lane & 15)) * RSB + ((lane & 16) ? 16u : 0u);
    const uint32_t boff = (uint32_t)((lane & 7) + ((lane & 8) ? 8 : 0)) * RSB + ((lane & 16) ? 16u : 0u);

    float oacc[32][4];
#pragma unroll
    for (int i = 0; i < 32; i++)
#pragma unroll
        for (int j = 0; j < 4; j++) oacc[i][j] = 0.f;

#pragma unroll 1
    for (int c = 0; c < 12; c++) {
        const int buf = c & 1;
        if (c < 11) {
            const int wsel = (c + 1) >> 2;
            const int k0 = ((c + 1) & 3) * 64;
            const size_t gbase = (size_t)wsel * DIM * DIM + (size_t)k0 * DIM;
#pragma unroll
            for (int i = 0; i < 8; i++) {
                int idx = tid + i * 256;
                int row = idx >> 5, c16 = idx & 31;
                uint32_t d = (uint32_t)row * RSB + c16 * 16;
                cp16(sW[buf ^ 1] + d, g_W16 + gbase + (size_t)row * DIM + c16 * 8);
            }
            CP_COMMIT();
            CP_WAIT(1);
        } else {
            CP_WAIT(0);
        }
        __syncthreads();

        // compute chunk c: 4 ksteps of 16
        const int kbase = (c & 3) * 64;
#pragma unroll
        for (int ks = 0; ks < 4; ks++) {
            uint32_t af[4];
            ldsm_x4(af, sX + aoff + (uint32_t)(kbase + ks * 16) * 2);
#pragma unroll
            for (int nt = 0; nt < 16; nt++) {
                uint32_t bf[4];
                uint32_t a = (uint32_t)ks * 16 * RSB + boff + (uint32_t)nt * 32;
                ldsm_x4_t(bf, sW[buf] + a);
#pragma unroll
                for (int h = 0; h < 2; h++)
                    mma_f16(oacc[nt * 2 + h], af, &bf[2 * h]);
            }
        }

        // ---- end of a weight: epilogue ----
        if ((c & 3) == 3) {
            const int wsel = c >> 2;
            const float* bias = (wsel == 0) ? bq : (wsel == 1) ? bk : bv;
            __half* dst = (wsel == 0) ? g_Q : (wsel == 1) ? g_K : g_V;
            const int r0 = m0 + 16 * w + (lane >> 2);
            const size_t base0 = (size_t)r0 * DIM + (lane & 3) * 2;
            const size_t base1 = base0 + (size_t)8 * DIM;
#pragma unroll
            for (int nto = 0; nto < 32; nto++) {
                const int col = nto * 8 + (lane & 3) * 2;
                float b0 = bias[col], b1 = bias[col + 1];
                *(uint32_t*)&dst[base0 + nto * 8] =
                    pack_h(__float2half_rn(oacc[nto][0] + b0),
                           __float2half_rn(oacc[nto][1] + b1));
                *(uint32_t*)&dst[base1 + nto * 8] =
                    pack_h(__float2half_rn(oacc[nto][2] + b0),
                           __float2half_rn(oacc[nto][3] + b1));
                oacc[nto][0] = oacc[nto][1] = oacc[nto][2] = oacc[nto][3] = 0.f;
            }
        }
        __syncthreads();
    }
}

// ---------------------------------------------------------------------------
// Attention (unchanged from R8, proven ~260us @ rel_err 2.5e-4):
// plain fp16 mma, 32-key tiles, triple-buffered {K,V}, one sync per tile.
// ---------------------------------------------------------------------------
#define AQ_OFF   0
#define ABUF_OFF (128 * RSB)
#define ABUF_STR (2 * 32 * RSB)
#define ATTN_SMEM (ABUF_OFF + 3 * ABUF_STR)  // 168960
#define NKT 128

__global__ __launch_bounds__(256, 1) void attn_mma(float* __restrict__ out)
{
    extern __shared__ char smem[];
    const uint32_t sb = smem_to_u32(smem);
    const int tid = threadIdx.x;
    const int lane = tid & 31;
    const int w = tid >> 5;
    const int b = blockIdx.y;
    const int q0 = blockIdx.x * 128;

    const uint32_t sQ = sb + AQ_OFF;
    const size_t kvbase = (size_t)b * SEQ * DIM;

#define ISSUE_TILE(tile, bs) do {                                          \
    const size_t _g = kvbase + (size_t)(tile) * 32 * DIM;                  \
    const uint32_t _bb = sb + ABUF_OFF + (uint32_t)(bs) * ABUF_STR;        \
    _Pragma("unroll")                                                      \
    for (int _i = 0; _i < 4; _i++) {                                       \
        int _idx = tid + _i * 256;                                         \
        int _row = _idx >> 5, _ch = _idx & 31;                             \
        uint32_t _d = (uint32_t)_row * RSB + _ch * 16;                     \
        size_t _go = _g + (size_t)_row * DIM + _ch * 8;                    \
        cp16(_bb + _d, g_K + _go);                                         \
        cp16(_bb + 32 * RSB + _d, g_V + _go);                              \
    }                                                                      \
} while (0)

    {
        const size_t qg = (size_t)(b * SEQ + q0) * DIM;
#pragma unroll
        for (int i = 0; i < 16; i++) {
            int idx = tid + i * 256;
            int row = idx >> 5, ch = idx & 31;
            uint32_t d = (uint32_t)row * RSB + ch * 16;
            cp16(sQ + d, g_Q + qg + (size_t)row * DIM + ch * 8);
        }
    }
    ISSUE_TILE(0, 0);
    CP_COMMIT();
    ISSUE_TILE(1, 1);
    CP_COMMIT();

    const uint32_t qoff = (uint32_t)(16 * w + (lane & 15)) * RSB + ((lane & 16) ? 16u : 0u);
    const uint32_t koff = (uint32_t)((lane & 7) + ((lane & 16) ? 8 : 0)) * RSB + ((lane & 8) ? 16u : 0u);
    const uint32_t voff = (uint32_t)((lane & 7) + ((lane & 8) ? 8 : 0)) * RSB + ((lane & 16) ? 16u : 0u);

    float oacc[32][4];
#pragma unroll
    for (int i = 0; i < 32; i++)
#pragma unroll
        for (int j = 0; j < 4; j++) oacc[i][j] = 0.f;
    float lsum0 = 0.f, lsum1 = 0.f;

    const float SC = 0.0625f * 1.4426950408889634f;

    int cb = 0, ib = 2;

#pragma unroll 1
    for (int t = 0; t < NKT; t++) {
        if (t < NKT - 1) { CP_WAIT(1); } else { CP_WAIT(0); }
        __syncthreads();
        if (t + 2 < NKT) { ISSUE_TILE(t + 2, ib); CP_COMMIT(); }

        const uint32_t bK = sb + ABUF_OFF + (uint32_t)cb * ABUF_STR;
        const uint32_t bV = bK + 32 * RSB;

        float sacc[4][4];
#pragma unroll
        for (int i = 0; i < 4; i++)
#pragma unroll
            for (int j = 0; j < 4; j++) sacc[i][j] = 0.f;

#pragma unroll 4
        for (int ks = 0; ks < 16; ks++) {
            uint32_t qf[4], kf[2][4];
            ldsm_x4(qf, sQ + qoff + ks * 32);
#pragma unroll
            for (int np = 0; np < 2; np++)
                ldsm_x4(kf[np], bK + koff + (uint32_t)np * 16 * RSB + ks * 32);
#pragma unroll
            for (int np = 0; np < 2; np++)
#pragma unroll
                for (int h = 0; h < 2; h++)
                    mma_f16(sacc[np * 2 + h], qf, &kf[np][2 * h]);
        }

        uint32_t Pf[2][4];
#pragma unroll
        for (int nt = 0; nt < 4; nt++) {
            float p0 = ex2f(sacc[nt][0] * SC);
            float p1 = ex2f(sacc[nt][1] * SC);
            float p2 = ex2f(sacc[nt][2] * SC);
            float p3 = ex2f(sacc[nt][3] * SC);
            lsum0 += p0 + p1;
            lsum1 += p2 + p3;
            const int j = nt >> 1, bs = (nt & 1) * 2;
            Pf[j][bs]     = pack_h(__float2half_rn(p0), __float2half_rn(p1));
            Pf[j][bs + 1] = pack_h(__float2half_rn(p2), __float2half_rn(p3));
        }

#pragma unroll
        for (int dblk = 0; dblk < 4; dblk++)
#pragma unroll
            for (int kc = 0; kc < 2; kc++) {
#pragma unroll
                for (int q = 0; q < 4; q++) {
                    uint32_t vf[4];
                    uint32_t a = (uint32_t)kc * 16 * RSB + voff + (uint32_t)(dblk * 64 + q * 16) * 2;
                    ldsm_x4_t(vf, bV + a);
#pragma unroll
                    for (int h = 0; h < 2; h++)
                        mma_f16(oacc[dblk * 8 + q * 2 + h], Pf[kc], &vf[2 * h]);
                }
            }

        cb = (cb == 2) ? 0 : cb + 1;
        ib = (ib == 2) ? 0 : ib + 1;
    }

    lsum0 += __shfl_xor_sync(0xffffffffu, lsum0, 1);
    lsum0 += __shfl_xor_sync(0xffffffffu, lsum0, 2);
    lsum1 += __shfl_xor_sync(0xffffffffu, lsum1, 1);
    lsum1 += __shfl_xor_sync(0xffffffffu, lsum1, 2);
    const float inv0 = 1.0f / lsum0;
    const float inv1 = 1.0f / lsum1;

    const int r0 = q0 + 16 * w + (lane >> 2);
    const size_t base0 = ((size_t)b * SEQ + r0) * DIM + (lane & 3) * 2;
    const size_t base1 = base0 + (size_t)8 * DIM;
#pragma unroll
    for (int nto = 0; nto < 32; nto++) {
        float2 v0 = make_float2(oacc[nto][0] * inv0, oacc[nto][1] * inv0);
        float2 v1 = make_float2(oacc[nto][2] * inv1, oacc[nto][3] * inv1);
        *(float2*)&out[base0 + nto * 8] = v0;
        *(float2*)&out[base1 + nto * 8] = v1;
    }
}

// ---------------------------------------------------------------------------
extern "C" void kernel_launch(void* const* d_in, const int* in_sizes, int n_in,
                              void* d_out, int out_size)
{
    const float* x  = (const float*)d_in[0];
    const float* Wk = (const float*)d_in[1];
    const float* bk = (const float*)d_in[2];
    const float* Wq = (const float*)d_in[3];
    const float* bq = (const float*)d_in[4];
    const float* Wv = (const float*)d_in[5];
    const float* bv = (const float*)d_in[6];
    float* out = (float*)d_out;

    conv_w_kernel<<<dim3(64, 3), 256>>>(Wq, Wk, Wv);

    cudaFuncSetAttribute(proj_mma, cudaFuncAttributeMaxDynamicSharedMemorySize,
                         PROJ_SMEM);
    proj_mma<<<BATCH * SEQ / 128, 256, PROJ_SMEM>>>(x, bq, bk, bv);

    cudaFuncSetAttribute(attn_mma, cudaFuncAttributeMaxDynamicSharedMemorySize,
                         ATTN_SMEM);
    attn_mma<<<dim3(SEQ / 128, BATCH), 256, ATTN_SMEM>>>(out);
}

// round 11
// speedup vs baseline: 2.7715x; 1.0445x over previous
#include <cuda_runtime.h>
#include <cuda_fp16.h>
#include <cstdint>

#define BATCH 4
#define SEQ   4096
#define DIM   256
#define RSB   528

// Attention operands: plain fp16, row-major
static __device__ __align__(16) __half g_Q[(size_t)BATCH * SEQ * DIM];
static __device__ __align__(16) __half g_K[(size_t)BATCH * SEQ * DIM];
static __device__ __align__(16) __half g_V[(size_t)BATCH * SEQ * DIM];
// Projection weights, fp16
static __device__ __align__(16) __half g_W16[3 * DIM * DIM];

// ---------------------------------------------------------------------------
__device__ __forceinline__ uint32_t smem_to_u32(const void* p) {
    uint32_t a;
    asm("{ .reg .u64 t; cvta.to.shared.u64 t, %1; cvt.u32.u64 %0, t; }"
        : "=r"(a) : "l"(p));
    return a;
}
__device__ __forceinline__ void mma_f16(float* d, const uint32_t* a, const uint32_t* b) {
    asm volatile(
        "mma.sync.aligned.m16n8k16.row.col.f32.f16.f16.f32 "
        "{%0,%1,%2,%3}, {%4,%5,%6,%7}, {%8,%9}, {%0,%1,%2,%3};"
        : "+f"(d[0]), "+f"(d[1]), "+f"(d[2]), "+f"(d[3])
        : "r"(a[0]), "r"(a[1]), "r"(a[2]), "r"(a[3]), "r"(b[0]), "r"(b[1]));
}
__device__ __forceinline__ void ldsm_x4(uint32_t* r, uint32_t addr) {
    asm volatile("ldmatrix.sync.aligned.m8n8.x4.shared.b16 {%0,%1,%2,%3}, [%4];"
        : "=r"(r[0]), "=r"(r[1]), "=r"(r[2]), "=r"(r[3]) : "r"(addr));
}
__device__ __forceinline__ void ldsm_x4_t(uint32_t* r, uint32_t addr) {
    asm volatile("ldmatrix.sync.aligned.m8n8.x4.trans.shared.b16 {%0,%1,%2,%3}, [%4];"
        : "=r"(r[0]), "=r"(r[1]), "=r"(r[2]), "=r"(r[3]) : "r"(addr));
}
__device__ __forceinline__ void cp16(uint32_t dst, const void* src) {
    asm volatile("cp.async.cg.shared.global [%0], [%1], 16;" :: "r"(dst), "l"(src));
}
#define CP_COMMIT() asm volatile("cp.async.commit_group;" ::: "memory")
#define CP_WAIT(n)  asm volatile("cp.async.wait_group %0;" :: "n"(n) : "memory")

__device__ __forceinline__ float ex2f(float x) {
    float y;
    asm("ex2.approx.ftz.f32 %0, %1;" : "=f"(y) : "f"(x));
    return y;
}
// one-instruction pack: low half = lo, high half = hi
__device__ __forceinline__ uint32_t cvt_h2(float lo, float hi) {
    uint32_t r;
    asm("cvt.rn.f16x2.f32 %0, %1, %2;" : "=r"(r) : "f"(hi), "f"(lo));
    return r;
}

// ---------------------------------------------------------------------------
// W convert: fp32 -> fp16
// ---------------------------------------------------------------------------
__global__ __launch_bounds__(256) void conv_w_kernel(
    const float* __restrict__ Wq, const float* __restrict__ Wk,
    const float* __restrict__ Wv)
{
    const int wsel = blockIdx.y;
    const float* W = (wsel == 0) ? Wq : (wsel == 1) ? Wk : Wv;
    int idx = (blockIdx.x * 256 + threadIdx.x) * 4;
    float4 v = *(const float4*)&W[idx];
    size_t base = (size_t)wsel * DIM * DIM + idx;
    *(uint2*)&g_W16[base] = make_uint2(cvt_h2(v.x, v.y), cvt_h2(v.z, v.w));
}

// ---------------------------------------------------------------------------
// Single-pass fp16 projections (proven ~35us in R9)
// ---------------------------------------------------------------------------
#define PX_OFF  0
#define PW_OFF  (128 * RSB)
#define PWBUF   (64 * RSB)
#define PROJ_SMEM (PW_OFF + 2 * PWBUF)

__global__ __launch_bounds__(256, 1) void proj_mma(
    const float* __restrict__ x,
    const float* __restrict__ bq, const float* __restrict__ bk,
    const float* __restrict__ bv)
{
    extern __shared__ char smem[];
    const uint32_t sb = smem_to_u32(smem);
    const int tid = threadIdx.x;
    const int lane = tid & 31;
    const int w = tid >> 5;
    const int m0 = blockIdx.x * 128;

    const uint32_t sX = sb + PX_OFF;
    uint32_t sW[2] = {sb + PW_OFF, sb + PW_OFF + PWBUF};

#pragma unroll
    for (int i = 0; i < 8; i++) {
        int idx = tid + i * 256;
        int row = idx >> 5, c16 = idx & 31;
        uint32_t d = (uint32_t)row * RSB + c16 * 16;
        cp16(sW[0] + d, g_W16 + (size_t)row * DIM + c16 * 8);
    }
    CP_COMMIT();

#pragma unroll
    for (int i = 0; i < 32; i++) {
        int idx = tid + i * 256;
        int row = idx >> 6, c4 = idx & 63;
        float4 v = *(const float4*)&x[(size_t)(m0 + row) * DIM + c4 * 4];
        uint32_t d = (uint32_t)row * RSB + c4 * 8;
        *(uint2*)(smem + PX_OFF + d) = make_uint2(cvt_h2(v.x, v.y), cvt_h2(v.z, v.w));
    }

    const uint32_t aoff = (uint32_t)(16 * w + (lane & 15)) * RSB + ((lane & 16) ? 16u : 0u);
    const uint32_t boff = (uint32_t)((lane & 7) + ((lane & 8) ? 8 : 0)) * RSB + ((lane & 16) ? 16u : 0u);

    float oacc[32][4];
#pragma unroll
    for (int i = 0; i < 32; i++)
#pragma unroll
        for (int j = 0; j < 4; j++) oacc[i][j] = 0.f;

#pragma unroll 1
    for (int c = 0; c < 12; c++) {
        const int buf = c & 1;
        if (c < 11) {
            const int wsel = (c + 1) >> 2;
            const int k0 = ((c + 1) & 3) * 64;
            const size_t gbase = (size_t)wsel * DIM * DIM + (size_t)k0 * DIM;
#pragma unroll
            for (int i = 0; i < 8; i++) {
                int idx = tid + i * 256;
                int row = idx >> 5, c16 = idx & 31;
                uint32_t d = (uint32_t)row * RSB + c16 * 16;
                cp16(sW[buf ^ 1] + d, g_W16 + gbase + (size_t)row * DIM + c16 * 8);
            }
            CP_COMMIT();
            CP_WAIT(1);
        } else {
            CP_WAIT(0);
        }
        __syncthreads();

        const int kbase = (c & 3) * 64;
#pragma unroll
        for (int ks = 0; ks < 4; ks++) {
            uint32_t af[4];
            ldsm_x4(af, sX + aoff + (uint32_t)(kbase + ks * 16) * 2);
#pragma unroll
            for (int nt = 0; nt < 16; nt++) {
                uint32_t bf[4];
                uint32_t a = (uint32_t)ks * 16 * RSB + boff + (uint32_t)nt * 32;
                ldsm_x4_t(bf, sW[buf] + a);
#pragma unroll
                for (int h = 0; h < 2; h++)
                    mma_f16(oacc[nt * 2 + h], af, &bf[2 * h]);
            }
        }

        if ((c & 3) == 3) {
            const int wsel = c >> 2;
            const float* bias = (wsel == 0) ? bq : (wsel == 1) ? bk : bv;
            __half* dst = (wsel == 0) ? g_Q : (wsel == 1) ? g_K : g_V;
            const int r0 = m0 + 16 * w + (lane >> 2);
            const size_t base0 = (size_t)r0 * DIM + (lane & 3) * 2;
            const size_t base1 = base0 + (size_t)8 * DIM;
#pragma unroll
            for (int nto = 0; nto < 32; nto++) {
                const int col = nto * 8 + (lane & 3) * 2;
                float b0 = bias[col], b1 = bias[col + 1];
                *(uint32_t*)&dst[base0 + nto * 8] =
                    cvt_h2(oacc[nto][0] + b0, oacc[nto][1] + b1);
                *(uint32_t*)&dst[base1 + nto * 8] =
                    cvt_h2(oacc[nto][2] + b0, oacc[nto][3] + b1);
                oacc[nto][0] = oacc[nto][1] = oacc[nto][2] = oacc[nto][3] = 0.f;
            }
        }
        __syncthreads();
    }
}

// ---------------------------------------------------------------------------
// Attention, fp16, software-pipelined: body = softmax(t); PV(t) || S(t+1).
// 32-key tiles, triple-buffered {K,V}, one syncthreads per tile.
// FIX vs R10: buf(t+1) = (cb+1)%3 (was mis-derived from ib).
// ---------------------------------------------------------------------------
#define AQ_OFF   0
#define ABUF_OFF (128 * RSB)
#define ABUF_STR (2 * 32 * RSB)
#define ATTN_SMEM (ABUF_OFF + 3 * ABUF_STR)  // 168960
#define NKT 128

__global__ __launch_bounds__(256, 1) void attn_mma(float* __restrict__ out)
{
    extern __shared__ char smem[];
    const uint32_t sb = smem_to_u32(smem);
    const int tid = threadIdx.x;
    const int lane = tid & 31;
    const int w = tid >> 5;
    const int b = blockIdx.y;
    const int q0 = blockIdx.x * 128;

    const uint32_t sQ = sb + AQ_OFF;
    const size_t kvbase = (size_t)b * SEQ * DIM;

#define ISSUE_TILE(tile, bs) do {                                          \
    const size_t _g = kvbase + (size_t)(tile) * 32 * DIM;                  \
    const uint32_t _bb = sb + ABUF_OFF + (uint32_t)(bs) * ABUF_STR;        \
    _Pragma("unroll")                                                      \
    for (int _i = 0; _i < 4; _i++) {                                       \
        int _idx = tid + _i * 256;                                         \
        int _row = _idx >> 5, _ch = _idx & 31;                             \
        uint32_t _d = (uint32_t)_row * RSB + _ch * 16;                     \
        size_t _go = _g + (size_t)_row * DIM + _ch * 8;                    \
        cp16(_bb + _d, g_K + _go);                                         \
        cp16(_bb + 32 * RSB + _d, g_V + _go);                              \
    }                                                                      \
} while (0)

    // prologue loads: Q + T0, then T1
    {
        const size_t qg = (size_t)(b * SEQ + q0) * DIM;
#pragma unroll
        for (int i = 0; i < 16; i++) {
            int idx = tid + i * 256;
            int row = idx >> 5, ch = idx & 31;
            uint32_t d = (uint32_t)row * RSB + ch * 16;
            cp16(sQ + d, g_Q + qg + (size_t)row * DIM + ch * 8);
        }
    }
    ISSUE_TILE(0, 0);
    CP_COMMIT();
    ISSUE_TILE(1, 1);
    CP_COMMIT();

    const uint32_t qoff = (uint32_t)(16 * w + (lane & 15)) * RSB + ((lane & 16) ? 16u : 0u);
    const uint32_t koff = (uint32_t)((lane & 7) + ((lane & 16) ? 8 : 0)) * RSB + ((lane & 8) ? 16u : 0u);
    const uint32_t voff = (uint32_t)((lane & 7) + ((lane & 8) ? 8 : 0)) * RSB + ((lane & 16) ? 16u : 0u);

    float oacc[32][4];
#pragma unroll
    for (int i = 0; i < 32; i++)
#pragma unroll
        for (int j = 0; j < 4; j++) oacc[i][j] = 0.f;
    float lsum0 = 0.f, lsum1 = 0.f;
    float sacc[4][4];
    uint32_t Pf[2][4];

    const float SC = 0.0625f * 1.4426950408889634f;

    // ---- prologue compute: S(0) ----
    CP_WAIT(1);                 // Q + T0 arrived
    __syncthreads();
#pragma unroll
    for (int i = 0; i < 4; i++)
#pragma unroll
        for (int j = 0; j < 4; j++) sacc[i][j] = 0.f;
    {
        const uint32_t bK = sb + ABUF_OFF;   // buf 0
#pragma unroll 4
        for (int ks = 0; ks < 16; ks++) {
            uint32_t qf[4], kf[2][4];
            ldsm_x4(qf, sQ + qoff + ks * 32);
#pragma unroll
            for (int np = 0; np < 2; np++)
                ldsm_x4(kf[np], bK + koff + (uint32_t)np * 16 * RSB + ks * 32);
#pragma unroll
            for (int np = 0; np < 2; np++)
#pragma unroll
                for (int h = 0; h < 2; h++)
                    mma_f16(sacc[np * 2 + h], qf, &kf[np][2 * h]);
        }
    }

    int cb = 0, ib = 2;   // cb = buf(t), ib = buf(t+2)

#pragma unroll 1
    for (int t = 0; t < NKT; t++) {
        // all issued tiles (incl. t+1) arrived; all warps past tile t-1 reads
        CP_WAIT(0);
        __syncthreads();
        if (t + 2 < NKT) { ISSUE_TILE(t + 2, ib); CP_COMMIT(); }

        const int nb = (cb == 2) ? 0 : cb + 1;            // buf(t+1)  [FIX]
        const uint32_t bV  = sb + ABUF_OFF + (uint32_t)cb * ABUF_STR + 32 * RSB;
        const uint32_t bKn = sb + ABUF_OFF + (uint32_t)nb * ABUF_STR;

        // ---- softmax(t): sacc -> Pf ----
#pragma unroll
        for (int nt = 0; nt < 4; nt++) {
            float p0 = ex2f(sacc[nt][0] * SC);
            float p1 = ex2f(sacc[nt][1] * SC);
            float p2 = ex2f(sacc[nt][2] * SC);
            float p3 = ex2f(sacc[nt][3] * SC);
            lsum0 += p0 + p1;
            lsum1 += p2 + p3;
            const int j = nt >> 1, bs = (nt & 1) * 2;
            Pf[j][bs]     = cvt_h2(p0, p1);
            Pf[j][bs + 1] = cvt_h2(p2, p3);
        }
#pragma unroll
        for (int i = 0; i < 4; i++)
#pragma unroll
            for (int j = 0; j < 4; j++) sacc[i][j] = 0.f;

        // ---- merged: PV(t) (32 q-iters) || S(t+1) (16 ksteps) ----
        if (t + 1 < NKT) {
#pragma unroll
            for (int ks = 0; ks < 16; ks++) {
                // S(t+1) kstep
                uint32_t qf[4], kf[2][4];
                ldsm_x4(qf, sQ + qoff + ks * 32);
#pragma unroll
                for (int np = 0; np < 2; np++)
                    ldsm_x4(kf[np], bKn + koff + (uint32_t)np * 16 * RSB + ks * 32);
#pragma unroll
                for (int np = 0; np < 2; np++)
#pragma unroll
                    for (int h = 0; h < 2; h++)
                        mma_f16(sacc[np * 2 + h], qf, &kf[np][2 * h]);
                // PV(t): two q-iterations
#pragma unroll
                for (int u = 0; u < 2; u++) {
                    const int i = ks * 2 + u;
                    const int dblk = i >> 3, kc = (i >> 2) & 1, q = i & 3;
                    uint32_t vf[4];
                    ldsm_x4_t(vf, bV + (uint32_t)kc * 16 * RSB + voff +
                                   (uint32_t)(dblk * 64 + q * 16) * 2);
                    mma_f16(oacc[dblk * 8 + q * 2 + 0], Pf[kc], &vf[0]);
                    mma_f16(oacc[dblk * 8 + q * 2 + 1], Pf[kc], &vf[2]);
                }
            }
        } else {
            // last tile: PV only
#pragma unroll
            for (int i = 0; i < 32; i++) {
                const int dblk = i >> 3, kc = (i >> 2) & 1, q = i & 3;
                uint32_t vf[4];
                ldsm_x4_t(vf, bV + (uint32_t)kc * 16 * RSB + voff +
                               (uint32_t)(dblk * 64 + q * 16) * 2);
                mma_f16(oacc[dblk * 8 + q * 2 + 0], Pf[kc], &vf[0]);
                mma_f16(oacc[dblk * 8 + q * 2 + 1], Pf[kc], &vf[2]);
            }
        }

        cb = (cb == 2) ? 0 : cb + 1;
        ib = (ib == 2) ? 0 : ib + 1;
    }

    // ---- epilogue ----
    lsum0 += __shfl_xor_sync(0xffffffffu, lsum0, 1);
    lsum0 += __shfl_xor_sync(0xffffffffu, lsum0, 2);
    lsum1 += __shfl_xor_sync(0xffffffffu, lsum1, 1);
    lsum1 += __shfl_xor_sync(0xffffffffu, lsum1, 2);
    const float inv0 = 1.0f / lsum0;
    const float inv1 = 1.0f / lsum1;

    const int r0 = q0 + 16 * w + (lane >> 2);
    const size_t base0 = ((size_t)b * SEQ + r0) * DIM + (lane & 3) * 2;
    const size_t base1 = base0 + (size_t)8 * DIM;
#pragma unroll
    for (int nto = 0; nto < 32; nto++) {
        float2 v0 = make_float2(oacc[nto][0] * inv0, oacc[nto][1] * inv0);
        float2 v1 = make_float2(oacc[nto][2] * inv1, oacc[nto][3] * inv1);
        *(float2*)&out[base0 + nto * 8] = v0;
        *(float2*)&out[base1 + nto * 8] = v1;
    }
}

// ---------------------------------------------------------------------------
extern "C" void kernel_launch(void* const* d_in, const int* in_sizes, int n_in,
                              void* d_out, int out_size)
{
    const float* x  = (const float*)d_in[0];
    const float* Wk = (const float*)d_in[1];
    const float* bk = (const float*)d_in[2];
    const float* Wq = (const float*)d_in[3];
    const float* bq = (const float*)d_in[4];
    const float* Wv = (const float*)d_in[5];
    const float* bv = (const float*)d_in[6];
    float* out = (float*)d_out;

    conv_w_kernel<<<dim3(64, 3), 256>>>(Wq, Wk, Wv);

    cudaFuncSetAttribute(proj_mma, cudaFuncAttributeMaxDynamicSharedMemorySize,
                         PROJ_SMEM);
    proj_mma<<<BATCH * SEQ / 128, 256, PROJ_SMEM>>>(x, bq, bk, bv);

    cudaFuncSetAttribute(attn_mma, cudaFuncAttributeMaxDynamicSharedMemorySize,
                         ATTN_SMEM);
    attn_mma<<<dim3(SEQ / 128, BATCH), 256, ATTN_SMEM>>>(out);
}

// round 12
// speedup vs baseline: 3.2203x; 1.1619x over previous
#include <cuda_runtime.h>
#include <cuda_fp16.h>
#include <cstdint>

#define BATCH 4
#define SEQ   4096
#define DIM   256
#define RSB   528

// Attention operands: plain fp16, row-major
static __device__ __align__(16) __half g_Q[(size_t)BATCH * SEQ * DIM];
static __device__ __align__(16) __half g_K[(size_t)BATCH * SEQ * DIM];
static __device__ __align__(16) __half g_V[(size_t)BATCH * SEQ * DIM];
// Projection weights, fp16
static __device__ __align__(16) __half g_W16[3 * DIM * DIM];

// ---------------------------------------------------------------------------
__device__ __forceinline__ uint32_t smem_to_u32(const void* p) {
    uint32_t a;
    asm("{ .reg .u64 t; cvta.to.shared.u64 t, %1; cvt.u32.u64 %0, t; }"
        : "=r"(a) : "l"(p));
    return a;
}
__device__ __forceinline__ void mma_f16(float* d, const uint32_t* a, const uint32_t* b) {
    asm volatile(
        "mma.sync.aligned.m16n8k16.row.col.f32.f16.f16.f32 "
        "{%0,%1,%2,%3}, {%4,%5,%6,%7}, {%8,%9}, {%0,%1,%2,%3};"
        : "+f"(d[0]), "+f"(d[1]), "+f"(d[2]), "+f"(d[3])
        : "r"(a[0]), "r"(a[1]), "r"(a[2]), "r"(a[3]), "r"(b[0]), "r"(b[1]));
}
__device__ __forceinline__ void ldsm_x4(uint32_t* r, uint32_t addr) {
    asm volatile("ldmatrix.sync.aligned.m8n8.x4.shared.b16 {%0,%1,%2,%3}, [%4];"
        : "=r"(r[0]), "=r"(r[1]), "=r"(r[2]), "=r"(r[3]) : "r"(addr));
}
__device__ __forceinline__ void ldsm_x4_t(uint32_t* r, uint32_t addr) {
    asm volatile("ldmatrix.sync.aligned.m8n8.x4.trans.shared.b16 {%0,%1,%2,%3}, [%4];"
        : "=r"(r[0]), "=r"(r[1]), "=r"(r[2]), "=r"(r[3]) : "r"(addr));
}
__device__ __forceinline__ void cp16(uint32_t dst, const void* src) {
    asm volatile("cp.async.cg.shared.global [%0], [%1], 16;" :: "r"(dst), "l"(src));
}
#define CP_COMMIT() asm volatile("cp.async.commit_group;" ::: "memory")
#define CP_WAIT(n)  asm volatile("cp.async.wait_group %0;" :: "n"(n) : "memory")

__device__ __forceinline__ float ex2f(float x) {
    float y;
    asm("ex2.approx.ftz.f32 %0, %1;" : "=f"(y) : "f"(x));
    return y;
}
// one-instruction pack: low half = lo, high half = hi
__device__ __forceinline__ uint32_t cvt_h2(float lo, float hi) {
    uint32_t r;
    asm("cvt.rn.f16x2.f32 %0, %1, %2;" : "=r"(r) : "f"(hi), "f"(lo));
    return r;
}

// ---------------------------------------------------------------------------
// W convert: fp32 -> fp16
// ---------------------------------------------------------------------------
__global__ __launch_bounds__(256) void conv_w_kernel(
    const float* __restrict__ Wq, const float* __restrict__ Wk,
    const float* __restrict__ Wv)
{
    const int wsel = blockIdx.y;
    const float* W = (wsel == 0) ? Wq : (wsel == 1) ? Wk : Wv;
    int idx = (blockIdx.x * 256 + threadIdx.x) * 4;
    float4 v = *(const float4*)&W[idx];
    size_t base = (size_t)wsel * DIM * DIM + idx;
    *(uint2*)&g_W16[base] = make_uint2(cvt_h2(v.x, v.y), cvt_h2(v.z, v.w));
}

// ---------------------------------------------------------------------------
// Single-pass fp16 projections (proven ~35us)
// ---------------------------------------------------------------------------
#define PX_OFF  0
#define PW_OFF  (128 * RSB)
#define PWBUF   (64 * RSB)
#define PROJ_SMEM (PW_OFF + 2 * PWBUF)

__global__ __launch_bounds__(256, 1) void proj_mma(
    const float* __restrict__ x,
    const float* __restrict__ bq, const float* __restrict__ bk,
    const float* __restrict__ bv)
{
    extern __shared__ char smem[];
    const uint32_t sb = smem_to_u32(smem);
    const int tid = threadIdx.x;
    const int lane = tid & 31;
    const int w = tid >> 5;
    const int m0 = blockIdx.x * 128;

    const uint32_t sX = sb + PX_OFF;
    uint32_t sW[2] = {sb + PW_OFF, sb + PW_OFF + PWBUF};

#pragma unroll
    for (int i = 0; i < 8; i++) {
        int idx = tid + i * 256;
        int row = idx >> 5, c16 = idx & 31;
        uint32_t d = (uint32_t)row * RSB + c16 * 16;
        cp16(sW[0] + d, g_W16 + (size_t)row * DIM + c16 * 8);
    }
    CP_COMMIT();

#pragma unroll
    for (int i = 0; i < 32; i++) {
        int idx = tid + i * 256;
        int row = idx >> 6, c4 = idx & 63;
        float4 v = *(const float4*)&x[(size_t)(m0 + row) * DIM + c4 * 4];
        uint32_t d = (uint32_t)row * RSB + c4 * 8;
        *(uint2*)(smem + PX_OFF + d) = make_uint2(cvt_h2(v.x, v.y), cvt_h2(v.z, v.w));
    }

    const uint32_t aoff = (uint32_t)(16 * w + (lane & 15)) * RSB + ((lane & 16) ? 16u : 0u);
    const uint32_t boff = (uint32_t)((lane & 7) + ((lane & 8) ? 8 : 0)) * RSB + ((lane & 16) ? 16u : 0u);

    float oacc[32][4];
#pragma unroll
    for (int i = 0; i < 32; i++)
#pragma unroll
        for (int j = 0; j < 4; j++) oacc[i][j] = 0.f;

#pragma unroll 1
    for (int c = 0; c < 12; c++) {
        const int buf = c & 1;
        if (c < 11) {
            const int wsel = (c + 1) >> 2;
            const int k0 = ((c + 1) & 3) * 64;
            const size_t gbase = (size_t)wsel * DIM * DIM + (size_t)k0 * DIM;
#pragma unroll
            for (int i = 0; i < 8; i++) {
                int idx = tid + i * 256;
                int row = idx >> 5, c16 = idx & 31;
                uint32_t d = (uint32_t)row * RSB + c16 * 16;
                cp16(sW[buf ^ 1] + d, g_W16 + gbase + (size_t)row * DIM + c16 * 8);
            }
            CP_COMMIT();
            CP_WAIT(1);
        } else {
            CP_WAIT(0);
        }
        __syncthreads();

        const int kbase = (c & 3) * 64;
#pragma unroll
        for (int ks = 0; ks < 4; ks++) {
            uint32_t af[4];
            ldsm_x4(af, sX + aoff + (uint32_t)(kbase + ks * 16) * 2);
#pragma unroll
            for (int nt = 0; nt < 16; nt++) {
                uint32_t bf[4];
                uint32_t a = (uint32_t)ks * 16 * RSB + boff + (uint32_t)nt * 32;
                ldsm_x4_t(bf, sW[buf] + a);
#pragma unroll
                for (int h = 0; h < 2; h++)
                    mma_f16(oacc[nt * 2 + h], af, &bf[2 * h]);
            }
        }

        if ((c & 3) == 3) {
            const int wsel = c >> 2;
            const float* bias = (wsel == 0) ? bq : (wsel == 1) ? bk : bv;
            __half* dst = (wsel == 0) ? g_Q : (wsel == 1) ? g_K : g_V;
            const int r0 = m0 + 16 * w + (lane >> 2);
            const size_t base0 = (size_t)r0 * DIM + (lane & 3) * 2;
            const size_t base1 = base0 + (size_t)8 * DIM;
#pragma unroll
            for (int nto = 0; nto < 32; nto++) {
                const int col = nto * 8 + (lane & 3) * 2;
                float b0 = bias[col], b1 = bias[col + 1];
                *(uint32_t*)&dst[base0 + nto * 8] =
                    cvt_h2(oacc[nto][0] + b0, oacc[nto][1] + b1);
                *(uint32_t*)&dst[base1 + nto * 8] =
                    cvt_h2(oacc[nto][2] + b0, oacc[nto][3] + b1);
                oacc[nto][0] = oacc[nto][1] = oacc[nto][2] = oacc[nto][3] = 0.f;
            }
        }
        __syncthreads();
    }
}

// ---------------------------------------------------------------------------
// Attention: fp16 mma, pipelined (softmax(t); PV(t) || S(t+1)),
// Q register-resident (64 regs/thread), triple-buffered {K,V}.
// ---------------------------------------------------------------------------
#define AQ_OFF   0
#define ABUF_OFF (128 * RSB)
#define ABUF_STR (2 * 32 * RSB)
#define ATTN_SMEM (ABUF_OFF + 3 * ABUF_STR)  // 168960
#define NKT 128

__global__ __launch_bounds__(256, 1) void attn_mma(float* __restrict__ out)
{
    extern __shared__ char smem[];
    const uint32_t sb = smem_to_u32(smem);
    const int tid = threadIdx.x;
    const int lane = tid & 31;
    const int w = tid >> 5;
    const int b = blockIdx.y;
    const int q0 = blockIdx.x * 128;

    const uint32_t sQ = sb + AQ_OFF;
    const size_t kvbase = (size_t)b * SEQ * DIM;

#define ISSUE_TILE(tile, bs) do {                                          \
    const size_t _g = kvbase + (size_t)(tile) * 32 * DIM;                  \
    const uint32_t _bb = sb + ABUF_OFF + (uint32_t)(bs) * ABUF_STR;        \
    _Pragma("unroll")                                                      \
    for (int _i = 0; _i < 4; _i++) {                                       \
        int _idx = tid + _i * 256;                                         \
        int _row = _idx >> 5, _ch = _idx & 31;                             \
        uint32_t _d = (uint32_t)_row * RSB + _ch * 16;                     \
        size_t _go = _g + (size_t)_row * DIM + _ch * 8;                    \
        cp16(_bb + _d, g_K + _go);                                         \
        cp16(_bb + 32 * RSB + _d, g_V + _go);                              \
    }                                                                      \
} while (0)

    // prologue loads: Q + T0, then T1
    {
        const size_t qg = (size_t)(b * SEQ + q0) * DIM;
#pragma unroll
        for (int i = 0; i < 16; i++) {
            int idx = tid + i * 256;
            int row = idx >> 5, ch = idx & 31;
            uint32_t d = (uint32_t)row * RSB + ch * 16;
            cp16(sQ + d, g_Q + qg + (size_t)row * DIM + ch * 8);
        }
    }
    ISSUE_TILE(0, 0);
    CP_COMMIT();
    ISSUE_TILE(1, 1);
    CP_COMMIT();

    const uint32_t qoff = (uint32_t)(16 * w + (lane & 15)) * RSB + ((lane & 16) ? 16u : 0u);
    const uint32_t koff = (uint32_t)((lane & 7) + ((lane & 16) ? 8 : 0)) * RSB + ((lane & 8) ? 16u : 0u);
    const uint32_t voff = (uint32_t)((lane & 7) + ((lane & 8) ? 8 : 0)) * RSB + ((lane & 16) ? 16u : 0u);

    float oacc[32][4];
#pragma unroll
    for (int i = 0; i < 32; i++)
#pragma unroll
        for (int j = 0; j < 4; j++) oacc[i][j] = 0.f;
    float lsum0 = 0.f, lsum1 = 0.f;
    float sacc[4][4];
    uint32_t Pf[2][4];

    const float SC = 0.0625f * 1.4426950408889634f;

    // ---- prologue: Q -> registers (once), then S(0) ----
    CP_WAIT(1);                 // Q + T0 arrived
    __syncthreads();

    uint32_t qreg[16][4];
#pragma unroll
    for (int ks = 0; ks < 16; ks++)
        ldsm_x4(qreg[ks], sQ + qoff + ks * 32);

#pragma unroll
    for (int i = 0; i < 4; i++)
#pragma unroll
        for (int j = 0; j < 4; j++) sacc[i][j] = 0.f;
    {
        const uint32_t bK = sb + ABUF_OFF;   // buf 0
#pragma unroll 4
        for (int ks = 0; ks < 16; ks++) {
            uint32_t kf[2][4];
#pragma unroll
            for (int np = 0; np < 2; np++)
                ldsm_x4(kf[np], bK + koff + (uint32_t)np * 16 * RSB + ks * 32);
#pragma unroll
            for (int np = 0; np < 2; np++)
#pragma unroll
                for (int h = 0; h < 2; h++)
                    mma_f16(sacc[np * 2 + h], qreg[ks], &kf[np][2 * h]);
        }
    }

    int cb = 0, ib = 2;   // cb = buf(t), ib = buf(t+2)

#pragma unroll 1
    for (int t = 0; t < NKT; t++) {
        CP_WAIT(0);
        __syncthreads();
        if (t + 2 < NKT) { ISSUE_TILE(t + 2, ib); CP_COMMIT(); }

        const int nb = (cb == 2) ? 0 : cb + 1;            // buf(t+1)
        const uint32_t bV  = sb + ABUF_OFF + (uint32_t)cb * ABUF_STR + 32 * RSB;
        const uint32_t bKn = sb + ABUF_OFF + (uint32_t)nb * ABUF_STR;

        // ---- softmax(t): sacc -> Pf ----
#pragma unroll
        for (int nt = 0; nt < 4; nt++) {
            float p0 = ex2f(sacc[nt][0] * SC);
            float p1 = ex2f(sacc[nt][1] * SC);
            float p2 = ex2f(sacc[nt][2] * SC);
            float p3 = ex2f(sacc[nt][3] * SC);
            lsum0 += p0 + p1;
            lsum1 += p2 + p3;
            const int j = nt >> 1, bs = (nt & 1) * 2;
            Pf[j][bs]     = cvt_h2(p0, p1);
            Pf[j][bs + 1] = cvt_h2(p2, p3);
        }
#pragma unroll
        for (int i = 0; i < 4; i++)
#pragma unroll
            for (int j = 0; j < 4; j++) sacc[i][j] = 0.f;

        // ---- merged: PV(t) || S(t+1) ----
        if (t + 1 < NKT) {
#pragma unroll
            for (int ks = 0; ks < 16; ks++) {
                uint32_t kf[2][4];
#pragma unroll
                for (int np = 0; np < 2; np++)
                    ldsm_x4(kf[np], bKn + koff + (uint32_t)np * 16 * RSB + ks * 32);
#pragma unroll
                for (int np = 0; np < 2; np++)
#pragma unroll
                    for (int h = 0; h < 2; h++)
                        mma_f16(sacc[np * 2 + h], qreg[ks], &kf[np][2 * h]);
#pragma unroll
                for (int u = 0; u < 2; u++) {
                    const int i = ks * 2 + u;
                    const int dblk = i >> 3, kc = (i >> 2) & 1, q = i & 3;
                    uint32_t vf[4];
                    ldsm_x4_t(vf, bV + (uint32_t)kc * 16 * RSB + voff +
                                   (uint32_t)(dblk * 64 + q * 16) * 2);
                    mma_f16(oacc[dblk * 8 + q * 2 + 0], Pf[kc], &vf[0]);
                    mma_f16(oacc[dblk * 8 + q * 2 + 1], Pf[kc], &vf[2]);
                }
            }
        } else {
#pragma unroll
            for (int i = 0; i < 32; i++) {
                const int dblk = i >> 3, kc = (i >> 2) & 1, q = i & 3;
                uint32_t vf[4];
                ldsm_x4_t(vf, bV + (uint32_t)kc * 16 * RSB + voff +
                               (uint32_t)(dblk * 64 + q * 16) * 2);
                mma_f16(oacc[dblk * 8 + q * 2 + 0], Pf[kc], &vf[0]);
                mma_f16(oacc[dblk * 8 + q * 2 + 1], Pf[kc], &vf[2]);
            }
        }

        cb = (cb == 2) ? 0 : cb + 1;
        ib = (ib == 2) ? 0 : ib + 1;
    }

    // ---- epilogue ----
    lsum0 += __shfl_xor_sync(0xffffffffu, lsum0, 1);
    lsum0 += __shfl_xor_sync(0xffffffffu, lsum0, 2);
    lsum1 += __shfl_xor_sync(0xffffffffu, lsum1, 1);
    lsum1 += __shfl_xor_sync(0xffffffffu, lsum1, 2);
    const float inv0 = 1.0f / lsum0;
    const float inv1 = 1.0f / lsum1;

    const int r0 = q0 + 16 * w + (lane >> 2);
    const size_t base0 = ((size_t)b * SEQ + r0) * DIM + (lane & 3) * 2;
    const size_t base1 = base0 + (size_t)8 * DIM;
#pragma unroll
    for (int nto = 0; nto < 32; nto++) {
        float2 v0 = make_float2(oacc[nto][0] * inv0, oacc[nto][1] * inv0);
        float2 v1 = make_float2(oacc[nto][2] * inv1, oacc[nto][3] * inv1);
        *(float2*)&out[base0 + nto * 8] = v0;
        *(float2*)&out[base1 + nto * 8] = v1;
    }
}

// ---------------------------------------------------------------------------
extern "C" void kernel_launch(void* const* d_in, const int* in_sizes, int n_in,
                              void* d_out, int out_size)
{
    const float* x  = (const float*)d_in[0];
    const float* Wk = (const float*)d_in[1];
    const float* bk = (const float*)d_in[2];
    const float* Wq = (const float*)d_in[3];
    const float* bq = (const float*)d_in[4];
    const float* Wv = (const float*)d_in[5];
    const float* bv = (const float*)d_in[6];
    float* out = (float*)d_out;

    conv_w_kernel<<<dim3(64, 3), 256>>>(Wq, Wk, Wv);

    cudaFuncSetAttribute(proj_mma, cudaFuncAttributeMaxDynamicSharedMemorySize,
                         PROJ_SMEM);
    proj_mma<<<BATCH * SEQ / 128, 256, PROJ_SMEM>>>(x, bq, bk, bv);

    cudaFuncSetAttribute(attn_mma, cudaFuncAttributeMaxDynamicSharedMemorySize,
                         ATTN_SMEM);
    attn_mma<<<dim3(SEQ / 128, BATCH), 256, ATTN_SMEM>>>(out);
}